// round 1
// baseline (speedup 1.0000x reference)
#include <cuda_runtime.h>
#include <math.h>

#define NUx 200000
#define NSx 50000
#define NEx 1000000
#define NMx 100000
#define Hx  128

// ---------------- scratch (device globals; no allocation allowed) ----------------
__device__ float g_xu  [(size_t)NUx * Hx];   // user input features (concat) [NU,128]
__device__ float g_aggU[(size_t)NUx * Hx];   // aggregation buffer for users
__device__ float g_aggS[(size_t)NSx * Hx];   // aggregation buffer for sellers
__device__ float g_u1  [(size_t)NUx * Hx];
__device__ float g_s1  [(size_t)NSx * Hx];
__device__ float g_u2  [(size_t)NUx * Hx];
__device__ float g_s2  [(size_t)NSx * Hx];
__device__ int   g_cntU[NUx];
__device__ int   g_cntS[NSx];

// ---------------- zero fill ----------------
__global__ void zero_kernel(float4* __restrict__ p, long long n4) {
    long long i = (long long)blockIdx.x * blockDim.x + threadIdx.x;
    if (i < n4) p[i] = make_float4(0.f, 0.f, 0.f, 0.f);
}

// ---------------- build x_u = [age_emb | gen_emb | feat] ----------------
__global__ void build_xu_kernel(const float* __restrict__ feat,
                                const int*   __restrict__ x1,
                                const float* __restrict__ age_emb,
                                const float* __restrict__ gen_emb) {
    int tid = blockIdx.x * blockDim.x + threadIdx.x;
    if (tid >= NUx * 32) return;
    int r = tid >> 5, c = tid & 31;
    float4 v;
    if (c < 8) {
        int a = x1[2 * r];
        v = ((const float4*)age_emb)[a * 8 + c];
    } else if (c < 16) {
        int g = x1[2 * r + 1];
        v = ((const float4*)gen_emb)[g * 8 + (c - 8)];
    } else {
        v = ((const float4*)feat)[(size_t)r * 16 + (c - 16)];
    }
    ((float4*)g_xu)[(size_t)r * 32 + c] = v;
}

// ---------------- degree counts ----------------
__global__ void count_kernel(const int* __restrict__ dst_user,
                             const int* __restrict__ dst_seller) {
    int e = blockIdx.x * blockDim.x + threadIdx.x;
    if (e >= NEx) return;
    atomicAdd(&g_cntU[dst_user[e]], 1);
    atomicAdd(&g_cntS[dst_seller[e]], 1);
}

// ---------------- edge scatter-add of raw features ----------------
// F4 = F/4 (float4 chunks per row), SH = log2(F4)
template<int F4, int SH>
__global__ void scatter_kernel(const float* __restrict__ feat,
                               const int*   __restrict__ src,
                               const int*   __restrict__ dst,
                               float*       __restrict__ agg) {
    long long tid = (long long)blockIdx.x * blockDim.x + threadIdx.x;
    if (tid >= (long long)NEx * F4) return;
    int e = (int)(tid >> SH);
    int c = (int)(tid & (F4 - 1));
    int s = src[e], d = dst[e];
    float4 v = ((const float4*)feat)[(size_t)s * F4 + c];
    float* o = agg + (size_t)d * (F4 * 4) + c * 4;
    atomicAdd(o + 0, v.x);
    atomicAdd(o + 1, v.y);
    atomicAdd(o + 2, v.z);
    atomicAdd(o + 3, v.w);
}

// ---------------- fused SAGE layer GEMM ----------------
// out[i,:] = relu( (agg[i,:]/max(cnt[i],1)) @ Wl + xr[i,:] @ Wr + bias ),  out width = 128
// block: 256 threads = 64 row-slots x 4 col-groups; 2 rows per thread (128 rows/block)
// col-group cg owns interleaved columns j4*16 + cg*4 + {0..3}  (conflict-free LDS.128)
template<int FA, int FB>
__global__ void __launch_bounds__(256)
gemm_fused(const float* __restrict__ agg, const int* __restrict__ cnt,
           const float* __restrict__ xr,
           const float* __restrict__ Wl, const float* __restrict__ Wr,
           const float* __restrict__ bias,
           float* __restrict__ out, int N)
{
    extern __shared__ float sW[];   // FA*128 then FB*128
    const int tid = threadIdx.x;
    for (int i = tid; i < FA * Hx; i += 256) sW[i] = Wl[i];
    for (int i = tid; i < FB * Hx; i += 256) sW[FA * Hx + i] = Wr[i];
    __syncthreads();

    const int cg = tid & 3;
    const int rs = tid >> 2;
    const int row0 = blockIdx.x * 128 + rs;
    const int row1 = row0 + 64;
    const bool v0 = row0 < N, v1 = row1 < N;
    const int r0s = v0 ? row0 : 0;
    const int r1s = v1 ? row1 : 0;
    const float sc0 = v0 ? 1.f : 0.f;
    const float sc1 = v1 ? 1.f : 0.f;

    float inv0, inv1;
    { int c0 = cnt[r0s]; inv0 = sc0 / (float)(c0 > 1 ? c0 : 1);
      int c1 = cnt[r1s]; inv1 = sc1 / (float)(c1 > 1 ? c1 : 1); }

    float acc0[32], acc1[32];
#pragma unroll
    for (int j = 0; j < 32; j++) { acc0[j] = 0.f; acc1[j] = 0.f; }

    const float4* sW4 = (const float4*)sW;

    // ---- pass A: mean-aggregated neighbors ----
    {
        const float4* a0p = (const float4*)(agg + (size_t)r0s * FA);
        const float4* a1p = (const float4*)(agg + (size_t)r1s * FA);
        for (int k4 = 0; k4 < FA / 4; k4++) {
            float4 A0 = a0p[k4];
            float4 A1 = a1p[k4];
            float a0[4] = {A0.x * inv0, A0.y * inv0, A0.z * inv0, A0.w * inv0};
            float a1[4] = {A1.x * inv1, A1.y * inv1, A1.z * inv1, A1.w * inv1};
#pragma unroll
            for (int kk = 0; kk < 4; kk++) {
                const int k = k4 * 4 + kk;
#pragma unroll
                for (int j4 = 0; j4 < 8; j4++) {
                    float4 w = sW4[k * 32 + j4 * 4 + cg];
                    acc0[j4*4+0] += a0[kk] * w.x;
                    acc0[j4*4+1] += a0[kk] * w.y;
                    acc0[j4*4+2] += a0[kk] * w.z;
                    acc0[j4*4+3] += a0[kk] * w.w;
                    acc1[j4*4+0] += a1[kk] * w.x;
                    acc1[j4*4+1] += a1[kk] * w.y;
                    acc1[j4*4+2] += a1[kk] * w.z;
                    acc1[j4*4+3] += a1[kk] * w.w;
                }
            }
        }
    }
    // ---- pass B: self features ----
    {
        const float4* x0p = (const float4*)(xr + (size_t)r0s * FB);
        const float4* x1p = (const float4*)(xr + (size_t)r1s * FB);
        const float4* sWr4 = sW4 + FA * 32;
        for (int k4 = 0; k4 < FB / 4; k4++) {
            float4 A0 = x0p[k4];
            float4 A1 = x1p[k4];
            float a0[4] = {A0.x * sc0, A0.y * sc0, A0.z * sc0, A0.w * sc0};
            float a1[4] = {A1.x * sc1, A1.y * sc1, A1.z * sc1, A1.w * sc1};
#pragma unroll
            for (int kk = 0; kk < 4; kk++) {
                const int k = k4 * 4 + kk;
#pragma unroll
                for (int j4 = 0; j4 < 8; j4++) {
                    float4 w = sWr4[k * 32 + j4 * 4 + cg];
                    acc0[j4*4+0] += a0[kk] * w.x;
                    acc0[j4*4+1] += a0[kk] * w.y;
                    acc0[j4*4+2] += a0[kk] * w.z;
                    acc0[j4*4+3] += a0[kk] * w.w;
                    acc1[j4*4+0] += a1[kk] * w.x;
                    acc1[j4*4+1] += a1[kk] * w.y;
                    acc1[j4*4+2] += a1[kk] * w.z;
                    acc1[j4*4+3] += a1[kk] * w.w;
                }
            }
        }
    }

    // ---- epilogue: bias + relu ----
    if (v0) {
#pragma unroll
        for (int j4 = 0; j4 < 8; j4++) {
            float4 b = ((const float4*)bias)[j4 * 4 + cg];
            float4 o;
            o.x = fmaxf(acc0[j4*4+0] + b.x, 0.f);
            o.y = fmaxf(acc0[j4*4+1] + b.y, 0.f);
            o.z = fmaxf(acc0[j4*4+2] + b.z, 0.f);
            o.w = fmaxf(acc0[j4*4+3] + b.w, 0.f);
            ((float4*)out)[(size_t)row0 * 32 + j4 * 4 + cg] = o;
        }
    }
    if (v1) {
#pragma unroll
        for (int j4 = 0; j4 < 8; j4++) {
            float4 b = ((const float4*)bias)[j4 * 4 + cg];
            float4 o;
            o.x = fmaxf(acc1[j4*4+0] + b.x, 0.f);
            o.y = fmaxf(acc1[j4*4+1] + b.y, 0.f);
            o.z = fmaxf(acc1[j4*4+2] + b.z, 0.f);
            o.w = fmaxf(acc1[j4*4+3] + b.w, 0.f);
            ((float4*)out)[(size_t)row1 * 32 + j4 * 4 + cg] = o;
        }
    }
}

// ---------------- head: gather rows, dot with lin_w, sigmoid ----------------
__global__ void final_kernel(const int* __restrict__ mu, const int* __restrict__ ms,
                             const float* __restrict__ lw, const float* __restrict__ lb,
                             float* __restrict__ out) {
    int t = blockIdx.x * blockDim.x + threadIdx.x;
    int m = t >> 5, lane = t & 31;
    if (m >= NMx) return;
    int iu = mu[m], is_ = ms[m];
    float4 a  = ((const float4*)g_u2)[(size_t)iu  * 32 + lane];
    float4 w  = ((const float4*)lw)[lane];
    float s = a.x * w.x + a.y * w.y + a.z * w.z + a.w * w.w;
    float4 b  = ((const float4*)g_s2)[(size_t)is_ * 32 + lane];
    float4 w2 = ((const float4*)lw)[32 + lane];
    s += b.x * w2.x + b.y * w2.y + b.z * w2.z + b.w * w2.w;
#pragma unroll
    for (int o = 16; o; o >>= 1) s += __shfl_down_sync(0xffffffffu, s, o);
    if (lane == 0) out[m] = 1.f / (1.f + expf(-(s + lb[0])));
}

// ---------------- launcher ----------------
extern "C" void kernel_launch(void* const* d_in, const int* in_sizes, int n_in,
                              void* d_out, int out_size) {
    (void)in_sizes; (void)n_in; (void)out_size;
    const float* x_user_feat   = (const float*)d_in[0];
    const float* x_seller_feat = (const float*)d_in[1];
    const int*   x1            = (const int*)  d_in[2];
    const int*   src_user      = (const int*)  d_in[3];
    const int*   dst_seller    = (const int*)  d_in[4];
    const int*   src_seller    = (const int*)  d_in[5];
    const int*   dst_user      = (const int*)  d_in[6];
    const int*   mask_user     = (const int*)  d_in[7];
    const int*   mask_seller   = (const int*)  d_in[8];
    const float* age_emb       = (const float*)d_in[9];
    const float* gen_emb       = (const float*)d_in[10];
    const float* W1ul = (const float*)d_in[11];
    const float* W1ur = (const float*)d_in[12];
    const float* b1u  = (const float*)d_in[13];
    const float* W1sl = (const float*)d_in[14];
    const float* W1sr = (const float*)d_in[15];
    const float* b1s  = (const float*)d_in[16];
    const float* W2ul = (const float*)d_in[17];
    const float* W2ur = (const float*)d_in[18];
    const float* b2u  = (const float*)d_in[19];
    const float* W2sl = (const float*)d_in[20];
    const float* W2sr = (const float*)d_in[21];
    const float* b2s  = (const float*)d_in[22];
    const float* lin_w = (const float*)d_in[23];
    const float* lin_b = (const float*)d_in[24];
    float* out = (float*)d_out;

    float *xu, *aggU, *aggS, *u1, *s1, *u2, *s2;
    int *cntU, *cntS;
    cudaGetSymbolAddress((void**)&xu,   g_xu);
    cudaGetSymbolAddress((void**)&aggU, g_aggU);
    cudaGetSymbolAddress((void**)&aggS, g_aggS);
    cudaGetSymbolAddress((void**)&u1,   g_u1);
    cudaGetSymbolAddress((void**)&s1,   g_s1);
    cudaGetSymbolAddress((void**)&u2,   g_u2);
    cudaGetSymbolAddress((void**)&s2,   g_s2);
    cudaGetSymbolAddress((void**)&cntU, g_cntU);
    cudaGetSymbolAddress((void**)&cntS, g_cntS);

    cudaFuncSetAttribute(gemm_fused<64,128>,  cudaFuncAttributeMaxDynamicSharedMemorySize, (64+128)*Hx*4);
    cudaFuncSetAttribute(gemm_fused<128,64>,  cudaFuncAttributeMaxDynamicSharedMemorySize, (128+64)*Hx*4);
    cudaFuncSetAttribute(gemm_fused<128,128>, cudaFuncAttributeMaxDynamicSharedMemorySize, (128+128)*Hx*4);

    const int T = 256;

    // zero agg buffers + counts
    zero_kernel<<<(NUx*32 + T - 1) / T, T>>>((float4*)aggU, (long long)NUx * 32);
    zero_kernel<<<(NSx*32 + T - 1) / T, T>>>((float4*)aggS, (long long)NSx * 32);
    zero_kernel<<<(NUx/4  + T - 1) / T, T>>>((float4*)cntU, NUx / 4);
    zero_kernel<<<(NSx/4  + T - 1) / T, T>>>((float4*)cntS, NSx / 4);

    // build user input features, degree counts
    build_xu_kernel<<<(NUx*32 + T - 1) / T, T>>>(x_user_feat, x1, age_emb, gen_emb);
    count_kernel<<<(NEx + T - 1) / T, T>>>(dst_user, dst_seller);

    // layer 1 aggregation: sellers->users (64f), users->sellers (128f)
    scatter_kernel<16,4><<<(int)(((long long)NEx*16 + T - 1) / T), T>>>(x_seller_feat, src_seller, dst_user,   aggU);
    scatter_kernel<32,5><<<(int)(((long long)NEx*32 + T - 1) / T), T>>>(xu,            src_user,   dst_seller, aggS);

    // layer 1 dense
    gemm_fused<64,128><<<(NUx + 127) / 128, 256, (64+128)*Hx*4>>>(aggU, cntU, xu,            W1ul, W1ur, b1u, u1, NUx);
    gemm_fused<128,64><<<(NSx + 127) / 128, 256, (128+64)*Hx*4>>>(aggS, cntS, x_seller_feat, W1sl, W1sr, b1s, s1, NSx);

    // layer 2 aggregation
    zero_kernel<<<(NUx*32 + T - 1) / T, T>>>((float4*)aggU, (long long)NUx * 32);
    zero_kernel<<<(NSx*32 + T - 1) / T, T>>>((float4*)aggS, (long long)NSx * 32);
    scatter_kernel<32,5><<<(int)(((long long)NEx*32 + T - 1) / T), T>>>(s1, src_seller, dst_user,   aggU);
    scatter_kernel<32,5><<<(int)(((long long)NEx*32 + T - 1) / T), T>>>(u1, src_user,   dst_seller, aggS);

    // layer 2 dense
    gemm_fused<128,128><<<(NUx + 127) / 128, 256, (128+128)*Hx*4>>>(aggU, cntU, u1, W2ul, W2ur, b2u, u2, NUx);
    gemm_fused<128,128><<<(NSx + 127) / 128, 256, (128+128)*Hx*4>>>(aggS, cntS, s1, W2sl, W2sr, b2s, s2, NSx);

    // head
    final_kernel<<<(NMx*32 + T - 1) / T, T>>>(mask_user, mask_seller, lin_w, lin_b, out);
}

// round 2
// speedup vs baseline: 1.2872x; 1.2872x over previous
#include <cuda_runtime.h>
#include <math.h>

#define NUx 200000
#define NSx 50000
#define NEx 1000000
#define NMx 100000
#define Hx  128

// ---------------- scratch (device globals; no allocation allowed) ----------------
__device__ float g_xu  [(size_t)NUx * Hx];   // user input features (concat) [NU,128]
__device__ float g_aggU[(size_t)NUx * Hx];   // aggregation buffer for users
__device__ float g_aggS[(size_t)NSx * Hx];   // aggregation buffer for sellers
__device__ float g_u1  [(size_t)NUx * Hx];
__device__ float g_s1  [(size_t)NSx * Hx];
__device__ float g_u2  [(size_t)NUx * Hx];
__device__ float g_s2  [(size_t)NSx * Hx];
__device__ int   g_cntU[NUx];
__device__ int   g_cntS[NSx];

// ---------------- zero fill ----------------
__global__ void zero_kernel(float4* __restrict__ p, long long n4) {
    long long i = (long long)blockIdx.x * blockDim.x + threadIdx.x;
    if (i < n4) p[i] = make_float4(0.f, 0.f, 0.f, 0.f);
}

// ---------------- build x_u = [age_emb | gen_emb | feat] ----------------
__global__ void build_xu_kernel(const float* __restrict__ feat,
                                const int*   __restrict__ x1,
                                const float* __restrict__ age_emb,
                                const float* __restrict__ gen_emb) {
    int tid = blockIdx.x * blockDim.x + threadIdx.x;
    if (tid >= NUx * 32) return;
    int r = tid >> 5, c = tid & 31;
    float4 v;
    if (c < 8) {
        int a = x1[2 * r];
        v = ((const float4*)age_emb)[a * 8 + c];
    } else if (c < 16) {
        int g = x1[2 * r + 1];
        v = ((const float4*)gen_emb)[g * 8 + (c - 8)];
    } else {
        v = ((const float4*)feat)[(size_t)r * 16 + (c - 16)];
    }
    ((float4*)g_xu)[(size_t)r * 32 + c] = v;
}

// ---------------- edge scatter-add (warp-cooperative, vector red) ----------------
// LPE lanes per edge (16 for 64-wide rows, 32 for 128-wide). Each lane owns one
// float4 of the source row and issues ONE red.global.add.v4.f32 to the dst row.
// Optionally fuses degree counting (one int atomic per edge).
template<int LPE, bool COUNT>
__global__ void __launch_bounds__(256)
scatter_warp(const float* __restrict__ feat,
             const int*   __restrict__ src,
             const int*   __restrict__ dst,
             float*       __restrict__ agg,
             int*         __restrict__ cnt) {
    long long tid = (long long)blockIdx.x * blockDim.x + threadIdx.x;
    int e = (int)(tid >> (LPE == 32 ? 5 : 4));
    if (e >= NEx) return;
    int lane = threadIdx.x & 31;
    int sub = lane & (LPE - 1);
    int leader = lane & ~(LPE - 1);
    int s = 0, d = 0;
    if (sub == 0) { s = src[e]; d = dst[e]; }
    s = __shfl_sync(0xffffffffu, s, leader);
    d = __shfl_sync(0xffffffffu, d, leader);
    float4 v = ((const float4*)feat)[(size_t)s * LPE + sub];
    float* o = agg + (size_t)d * (LPE * 4) + sub * 4;
    asm volatile("red.global.add.v4.f32 [%0], {%1,%2,%3,%4};"
                 :: "l"(o), "f"(v.x), "f"(v.y), "f"(v.z), "f"(v.w)
                 : "memory");
    if (COUNT && sub == 0) atomicAdd(&cnt[d], 1);
}

// ---------------- fused SAGE layer GEMM ----------------
// out[i,:] = relu( (agg[i,:]/max(cnt[i],1)) @ Wl + xr[i,:] @ Wr + bias ),  out width = 128
// block: 256 threads = 64 row-slots x 4 col-groups; 2 rows per thread (128 rows/block)
template<int FA, int FB>
__global__ void __launch_bounds__(256)
gemm_fused(const float* __restrict__ agg, const int* __restrict__ cnt,
           const float* __restrict__ xr,
           const float* __restrict__ Wl, const float* __restrict__ Wr,
           const float* __restrict__ bias,
           float* __restrict__ out, int N)
{
    extern __shared__ float sW[];   // FA*128 then FB*128
    const int tid = threadIdx.x;
    for (int i = tid; i < FA * Hx; i += 256) sW[i] = Wl[i];
    for (int i = tid; i < FB * Hx; i += 256) sW[FA * Hx + i] = Wr[i];
    __syncthreads();

    const int cg = tid & 3;
    const int rs = tid >> 2;
    const int row0 = blockIdx.x * 128 + rs;
    const int row1 = row0 + 64;
    const bool v0 = row0 < N, v1 = row1 < N;
    const int r0s = v0 ? row0 : 0;
    const int r1s = v1 ? row1 : 0;
    const float sc0 = v0 ? 1.f : 0.f;
    const float sc1 = v1 ? 1.f : 0.f;

    float inv0, inv1;
    { int c0 = cnt[r0s]; inv0 = sc0 / (float)(c0 > 1 ? c0 : 1);
      int c1 = cnt[r1s]; inv1 = sc1 / (float)(c1 > 1 ? c1 : 1); }

    float acc0[32], acc1[32];
#pragma unroll
    for (int j = 0; j < 32; j++) { acc0[j] = 0.f; acc1[j] = 0.f; }

    const float4* sW4 = (const float4*)sW;

    // ---- pass A: mean-aggregated neighbors ----
    {
        const float4* a0p = (const float4*)(agg + (size_t)r0s * FA);
        const float4* a1p = (const float4*)(agg + (size_t)r1s * FA);
        for (int k4 = 0; k4 < FA / 4; k4++) {
            float4 A0 = a0p[k4];
            float4 A1 = a1p[k4];
            float a0[4] = {A0.x * inv0, A0.y * inv0, A0.z * inv0, A0.w * inv0};
            float a1[4] = {A1.x * inv1, A1.y * inv1, A1.z * inv1, A1.w * inv1};
#pragma unroll
            for (int kk = 0; kk < 4; kk++) {
                const int k = k4 * 4 + kk;
#pragma unroll
                for (int j4 = 0; j4 < 8; j4++) {
                    float4 w = sW4[k * 32 + j4 * 4 + cg];
                    acc0[j4*4+0] += a0[kk] * w.x;
                    acc0[j4*4+1] += a0[kk] * w.y;
                    acc0[j4*4+2] += a0[kk] * w.z;
                    acc0[j4*4+3] += a0[kk] * w.w;
                    acc1[j4*4+0] += a1[kk] * w.x;
                    acc1[j4*4+1] += a1[kk] * w.y;
                    acc1[j4*4+2] += a1[kk] * w.z;
                    acc1[j4*4+3] += a1[kk] * w.w;
                }
            }
        }
    }
    // ---- pass B: self features ----
    {
        const float4* x0p = (const float4*)(xr + (size_t)r0s * FB);
        const float4* x1p = (const float4*)(xr + (size_t)r1s * FB);
        const float4* sWr4 = sW4 + FA * 32;
        for (int k4 = 0; k4 < FB / 4; k4++) {
            float4 A0 = x0p[k4];
            float4 A1 = x1p[k4];
            float a0[4] = {A0.x * sc0, A0.y * sc0, A0.z * sc0, A0.w * sc0};
            float a1[4] = {A1.x * sc1, A1.y * sc1, A1.z * sc1, A1.w * sc1};
#pragma unroll
            for (int kk = 0; kk < 4; kk++) {
                const int k = k4 * 4 + kk;
#pragma unroll
                for (int j4 = 0; j4 < 8; j4++) {
                    float4 w = sWr4[k * 32 + j4 * 4 + cg];
                    acc0[j4*4+0] += a0[kk] * w.x;
                    acc0[j4*4+1] += a0[kk] * w.y;
                    acc0[j4*4+2] += a0[kk] * w.z;
                    acc0[j4*4+3] += a0[kk] * w.w;
                    acc1[j4*4+0] += a1[kk] * w.x;
                    acc1[j4*4+1] += a1[kk] * w.y;
                    acc1[j4*4+2] += a1[kk] * w.z;
                    acc1[j4*4+3] += a1[kk] * w.w;
                }
            }
        }
    }

    // ---- epilogue: bias + relu ----
    if (v0) {
#pragma unroll
        for (int j4 = 0; j4 < 8; j4++) {
            float4 b = ((const float4*)bias)[j4 * 4 + cg];
            float4 o;
            o.x = fmaxf(acc0[j4*4+0] + b.x, 0.f);
            o.y = fmaxf(acc0[j4*4+1] + b.y, 0.f);
            o.z = fmaxf(acc0[j4*4+2] + b.z, 0.f);
            o.w = fmaxf(acc0[j4*4+3] + b.w, 0.f);
            ((float4*)out)[(size_t)row0 * 32 + j4 * 4 + cg] = o;
        }
    }
    if (v1) {
#pragma unroll
        for (int j4 = 0; j4 < 8; j4++) {
            float4 b = ((const float4*)bias)[j4 * 4 + cg];
            float4 o;
            o.x = fmaxf(acc1[j4*4+0] + b.x, 0.f);
            o.y = fmaxf(acc1[j4*4+1] + b.y, 0.f);
            o.z = fmaxf(acc1[j4*4+2] + b.z, 0.f);
            o.w = fmaxf(acc1[j4*4+3] + b.w, 0.f);
            ((float4*)out)[(size_t)row1 * 32 + j4 * 4 + cg] = o;
        }
    }
}

// ---------------- head: gather rows, dot with lin_w, sigmoid ----------------
__global__ void final_kernel(const int* __restrict__ mu, const int* __restrict__ ms,
                             const float* __restrict__ lw, const float* __restrict__ lb,
                             float* __restrict__ out) {
    int t = blockIdx.x * blockDim.x + threadIdx.x;
    int m = t >> 5, lane = t & 31;
    if (m >= NMx) return;
    int iu = mu[m], is_ = ms[m];
    float4 a  = ((const float4*)g_u2)[(size_t)iu  * 32 + lane];
    float4 w  = ((const float4*)lw)[lane];
    float s = a.x * w.x + a.y * w.y + a.z * w.z + a.w * w.w;
    float4 b  = ((const float4*)g_s2)[(size_t)is_ * 32 + lane];
    float4 w2 = ((const float4*)lw)[32 + lane];
    s += b.x * w2.x + b.y * w2.y + b.z * w2.z + b.w * w2.w;
#pragma unroll
    for (int o = 16; o; o >>= 1) s += __shfl_down_sync(0xffffffffu, s, o);
    if (lane == 0) out[m] = 1.f / (1.f + expf(-(s + lb[0])));
}

// ---------------- launcher ----------------
extern "C" void kernel_launch(void* const* d_in, const int* in_sizes, int n_in,
                              void* d_out, int out_size) {
    (void)in_sizes; (void)n_in; (void)out_size;
    const float* x_user_feat   = (const float*)d_in[0];
    const float* x_seller_feat = (const float*)d_in[1];
    const int*   x1            = (const int*)  d_in[2];
    const int*   src_user      = (const int*)  d_in[3];
    const int*   dst_seller    = (const int*)  d_in[4];
    const int*   src_seller    = (const int*)  d_in[5];
    const int*   dst_user      = (const int*)  d_in[6];
    const int*   mask_user     = (const int*)  d_in[7];
    const int*   mask_seller   = (const int*)  d_in[8];
    const float* age_emb       = (const float*)d_in[9];
    const float* gen_emb       = (const float*)d_in[10];
    const float* W1ul = (const float*)d_in[11];
    const float* W1ur = (const float*)d_in[12];
    const float* b1u  = (const float*)d_in[13];
    const float* W1sl = (const float*)d_in[14];
    const float* W1sr = (const float*)d_in[15];
    const float* b1s  = (const float*)d_in[16];
    const float* W2ul = (const float*)d_in[17];
    const float* W2ur = (const float*)d_in[18];
    const float* b2u  = (const float*)d_in[19];
    const float* W2sl = (const float*)d_in[20];
    const float* W2sr = (const float*)d_in[21];
    const float* b2s  = (const float*)d_in[22];
    const float* lin_w = (const float*)d_in[23];
    const float* lin_b = (const float*)d_in[24];
    float* out = (float*)d_out;

    float *xu, *aggU, *aggS, *u1, *s1, *u2, *s2;
    int *cntU, *cntS;
    cudaGetSymbolAddress((void**)&xu,   g_xu);
    cudaGetSymbolAddress((void**)&aggU, g_aggU);
    cudaGetSymbolAddress((void**)&aggS, g_aggS);
    cudaGetSymbolAddress((void**)&u1,   g_u1);
    cudaGetSymbolAddress((void**)&s1,   g_s1);
    cudaGetSymbolAddress((void**)&u2,   g_u2);
    cudaGetSymbolAddress((void**)&s2,   g_s2);
    cudaGetSymbolAddress((void**)&cntU, g_cntU);
    cudaGetSymbolAddress((void**)&cntS, g_cntS);

    cudaFuncSetAttribute(gemm_fused<64,128>,  cudaFuncAttributeMaxDynamicSharedMemorySize, (64+128)*Hx*4);
    cudaFuncSetAttribute(gemm_fused<128,64>,  cudaFuncAttributeMaxDynamicSharedMemorySize, (128+64)*Hx*4);
    cudaFuncSetAttribute(gemm_fused<128,128>, cudaFuncAttributeMaxDynamicSharedMemorySize, (128+128)*Hx*4);

    const int T = 256;

    // zero agg buffers + counts
    zero_kernel<<<(NUx*32 + T - 1) / T, T>>>((float4*)aggU, (long long)NUx * 32);
    zero_kernel<<<(NSx*32 + T - 1) / T, T>>>((float4*)aggS, (long long)NSx * 32);
    zero_kernel<<<(NUx/4  + T - 1) / T, T>>>((float4*)cntU, NUx / 4);
    zero_kernel<<<(NSx/4  + T - 1) / T, T>>>((float4*)cntS, NSx / 4);

    // build user input features
    build_xu_kernel<<<(NUx*32 + T - 1) / T, T>>>(x_user_feat, x1, age_emb, gen_emb);

    // layer 1 aggregation (+fused degree counts):
    // sellers->users (64-wide, 16 lanes/edge), users->sellers (128-wide, 32 lanes/edge)
    scatter_warp<16,true><<<(int)(((long long)NEx*16 + T - 1) / T), T>>>(x_seller_feat, src_seller, dst_user,   aggU, cntU);
    scatter_warp<32,true><<<(int)(((long long)NEx*32 + T - 1) / T), T>>>(xu,            src_user,   dst_seller, aggS, cntS);

    // layer 1 dense
    gemm_fused<64,128><<<(NUx + 127) / 128, 256, (64+128)*Hx*4>>>(aggU, cntU, xu,            W1ul, W1ur, b1u, u1, NUx);
    gemm_fused<128,64><<<(NSx + 127) / 128, 256, (128+64)*Hx*4>>>(aggS, cntS, x_seller_feat, W1sl, W1sr, b1s, s1, NSx);

    // layer 2 aggregation
    zero_kernel<<<(NUx*32 + T - 1) / T, T>>>((float4*)aggU, (long long)NUx * 32);
    zero_kernel<<<(NSx*32 + T - 1) / T, T>>>((float4*)aggS, (long long)NSx * 32);
    scatter_warp<32,false><<<(int)(((long long)NEx*32 + T - 1) / T), T>>>(s1, src_seller, dst_user,   aggU, nullptr);
    scatter_warp<32,false><<<(int)(((long long)NEx*32 + T - 1) / T), T>>>(u1, src_user,   dst_seller, aggS, nullptr);

    // layer 2 dense
    gemm_fused<128,128><<<(NUx + 127) / 128, 256, (128+128)*Hx*4>>>(aggU, cntU, u1, W2ul, W2ur, b2u, u2, NUx);
    gemm_fused<128,128><<<(NSx + 127) / 128, 256, (128+128)*Hx*4>>>(aggS, cntS, s1, W2sl, W2sr, b2s, s2, NSx);

    // head
    final_kernel<<<(NMx*32 + T - 1) / T, T>>>(mask_user, mask_seller, lin_w, lin_b, out);
}

// round 4
// speedup vs baseline: 2.5062x; 1.9470x over previous
#include <cuda_runtime.h>
#include <math.h>
#include <stdint.h>

#define NUx 200000
#define NSx 50000
#define NEx 1000000
#define NMx 100000
#define Hx  128

// ---------------- scratch (device globals; no allocation allowed) ----------------
__device__ float g_xu  [(size_t)NUx * Hx];
__device__ float g_aggU[(size_t)NUx * Hx];
__device__ float g_aggS[(size_t)NSx * Hx];
__device__ float g_u1  [(size_t)NUx * Hx];
__device__ float g_s1  [(size_t)NSx * Hx];
__device__ float g_u2  [(size_t)NUx * Hx];
__device__ float g_s2  [(size_t)NSx * Hx];
__device__ int   g_cntU[NUx];
__device__ int   g_cntS[NSx];
__device__ uint32_t g_Bimg[4 * 32768];   // 4 tf32 weight images in mma fragment layout

__device__ __forceinline__ uint32_t f2tf32(float x) {
    uint32_t r;
    asm("cvt.rna.tf32.f32 %0, %1;" : "=r"(r) : "f"(x));
    return r;
}

// ---------------- zero fill ----------------
__global__ void zero_kernel(float4* __restrict__ p, long long n4) {
    long long i = (long long)blockIdx.x * blockDim.x + threadIdx.x;
    if (i < n4) p[i] = make_float4(0.f, 0.f, 0.f, 0.f);
}

// ---------------- build x_u = [age_emb | gen_emb | feat] ----------------
__global__ void build_xu_kernel(const float* __restrict__ feat,
                                const int*   __restrict__ x1,
                                const float* __restrict__ age_emb,
                                const float* __restrict__ gen_emb) {
    int tid = blockIdx.x * blockDim.x + threadIdx.x;
    if (tid >= NUx * 32) return;
    int r = tid >> 5, c = tid & 31;
    float4 v;
    if (c < 8) {
        int a = x1[2 * r];
        v = ((const float4*)age_emb)[a * 8 + c];
    } else if (c < 16) {
        int g = x1[2 * r + 1];
        v = ((const float4*)gen_emb)[g * 8 + (c - 8)];
    } else {
        v = ((const float4*)feat)[(size_t)r * 16 + (c - 16)];
    }
    ((float4*)g_xu)[(size_t)r * 32 + c] = v;
}

// ---------------- build tf32 weight image in m16n8k8 B-fragment layout ----------------
// b0 of lane L = B[k = L&3][n = L>>2 (+ntile*8)] ; b1 at k+4. kstep = k>>3.
// idx = ((ntile*(K/8) + kstep)*32 + lane)*2 + reg
__global__ void build_B_kernel(const float* __restrict__ Wl, const float* __restrict__ Wr,
                               int FA, int K, uint32_t* __restrict__ img) {
    int tid = blockIdx.x * blockDim.x + threadIdx.x;
    if (tid >= K * 128) return;
    int k = tid >> 7, n = tid & 127;
    float v = (k < FA) ? Wl[k * 128 + n] : Wr[(k - FA) * 128 + n];
    int ntile = n >> 3;
    int lane  = ((n & 7) << 2) | (k & 3);
    int reg   = (k >> 2) & 1;
    int kstep = k >> 3;
    img[((ntile * (K >> 3) + kstep) * 32 + lane) * 2 + reg] = f2tf32(v);
}

// ---------------- edge scatter-add (warp-cooperative, vector red) ----------------
template<int LPE, bool COUNT>
__global__ void __launch_bounds__(256)
scatter_warp(const float* __restrict__ feat,
             const int*   __restrict__ src,
             const int*   __restrict__ dst,
             float*       __restrict__ agg,
             int*         __restrict__ cnt) {
    long long tid = (long long)blockIdx.x * blockDim.x + threadIdx.x;
    int e = (int)(tid >> (LPE == 32 ? 5 : 4));
    if (e >= NEx) return;
    int lane = threadIdx.x & 31;
    int sub = lane & (LPE - 1);
    int leader = lane & ~(LPE - 1);
    int s = 0, d = 0;
    if (sub == 0) { s = src[e]; d = dst[e]; }
    s = __shfl_sync(0xffffffffu, s, leader);
    d = __shfl_sync(0xffffffffu, d, leader);
    float4 v = ((const float4*)feat)[(size_t)s * LPE + sub];
    float* o = agg + (size_t)d * (LPE * 4) + sub * 4;
    asm volatile("red.global.add.v4.f32 [%0], {%1,%2,%3,%4};"
                 :: "l"(o), "f"(v.x), "f"(v.y), "f"(v.z), "f"(v.w)
                 : "memory");
    if (COUNT && sub == 0) atomicAdd(&cnt[d], 1);
}

// ---------------- tf32 mma.sync fused SAGE GEMM ----------------
// CTA = 128 rows x 128 cols. 8 warps: (wid&3)=M strip of 32 rows, (wid>>2)=N half of 64.
// A staged in smem (tf32 bits, row-major, stride K+4 -> conflict-free LDS),
// B from global fragment image (coalesced LDG.64, double-buffered in regs).
template<int FA, int FB>
__global__ void __launch_bounds__(256, 1)
gemm_mma(const float* __restrict__ agg, const int* __restrict__ cnt,
         const float* __restrict__ xr, const uint32_t* __restrict__ Bfrag,
         const float* __restrict__ bias, float* __restrict__ out, int Nrows)
{
    constexpr int K   = FA + FB;
    constexpr int KS  = K / 8;
    constexpr int LDA = K + 4;

    extern __shared__ uint32_t sA[];   // [128][LDA] tf32 bits
    const int tid  = threadIdx.x;
    const int wid  = tid >> 5;
    const int lane = tid & 31;
    const int tile0 = blockIdx.x * 128;

    // ---- stage A (scale by 1/deg on agg part, tf32-convert) ----
    {
        const int row  = tid >> 1;
        const int half = tid & 1;
        int grow = tile0 + row; if (grow >= Nrows) grow = Nrows - 1;
        int c = cnt[grow];
        const float inv = 1.f / (float)(c > 1 ? c : 1);
        const float4* pa = (const float4*)(agg + (size_t)grow * FA);
        const float4* px = (const float4*)(xr  + (size_t)grow * FB);
#pragma unroll
        for (int j = 0; j < K / 8; j++) {
            int k4 = half * (K / 8) + j;
            int kf = k4 * 4;
            float4 v; float sc;
            if (kf < FA) { v = pa[k4]; sc = inv; }
            else         { v = px[k4 - FA / 4]; sc = 1.f; }
            uint4 t;
            t.x = f2tf32(v.x * sc); t.y = f2tf32(v.y * sc);
            t.z = f2tf32(v.z * sc); t.w = f2tf32(v.w * sc);
            *(uint4*)(sA + row * LDA + kf) = t;
        }
    }
    __syncthreads();

    const int wm = wid & 3;
    const int wn = wid >> 2;
    const int lr = lane >> 2;
    const int lc = lane & 3;

    float acc[2][8][4];
#pragma unroll
    for (int t = 0; t < 2; t++)
#pragma unroll
        for (int nt = 0; nt < 8; nt++)
#pragma unroll
            for (int q = 0; q < 4; q++) acc[t][nt][q] = 0.f;

    const uint32_t* Ab = sA + (wm * 32 + lr) * LDA + lc;
    const uint2* Bp = (const uint2*)Bfrag + (size_t)(wn * 8) * KS * 32 + lane;

    uint2 bc[8], bn[8];
#pragma unroll
    for (int nt = 0; nt < 8; nt++) bc[nt] = Bp[nt * KS * 32];

#pragma unroll
    for (int ks = 0; ks < KS; ks++) {
        if (ks + 1 < KS) {
#pragma unroll
            for (int nt = 0; nt < 8; nt++) bn[nt] = Bp[nt * KS * 32 + (ks + 1) * 32];
        }
        uint32_t a[2][4];
#pragma unroll
        for (int t = 0; t < 2; t++) {
            const uint32_t* p = Ab + t * 16 * LDA + ks * 8;
            a[t][0] = p[0];
            a[t][1] = p[8 * LDA];
            a[t][2] = p[4];
            a[t][3] = p[8 * LDA + 4];
        }
#pragma unroll
        for (int t = 0; t < 2; t++)
#pragma unroll
            for (int nt = 0; nt < 8; nt++) {
                asm volatile(
                    "mma.sync.aligned.m16n8k8.row.col.f32.tf32.tf32.f32 "
                    "{%0,%1,%2,%3}, {%4,%5,%6,%7}, {%8,%9}, {%0,%1,%2,%3};"
                    : "+f"(acc[t][nt][0]), "+f"(acc[t][nt][1]),
                      "+f"(acc[t][nt][2]), "+f"(acc[t][nt][3])
                    : "r"(a[t][0]), "r"(a[t][1]), "r"(a[t][2]), "r"(a[t][3]),
                      "r"(bc[nt].x), "r"(bc[nt].y));
            }
#pragma unroll
        for (int nt = 0; nt < 8; nt++) bc[nt] = bn[nt];
    }

    // ---- epilogue: bias + relu, STG.64 per row-pair fragment ----
#pragma unroll
    for (int nt = 0; nt < 8; nt++) {
        const int col = wn * 64 + nt * 8 + lc * 2;
        const float2 bv = *(const float2*)(bias + col);
#pragma unroll
        for (int t = 0; t < 2; t++) {
            int r0 = tile0 + wm * 32 + t * 16 + lr;
            if (r0 < Nrows) {
                float2 o;
                o.x = fmaxf(acc[t][nt][0] + bv.x, 0.f);
                o.y = fmaxf(acc[t][nt][1] + bv.y, 0.f);
                *(float2*)(out + (size_t)r0 * 128 + col) = o;
            }
            int r1 = r0 + 8;
            if (r1 < Nrows) {
                float2 o;
                o.x = fmaxf(acc[t][nt][2] + bv.x, 0.f);
                o.y = fmaxf(acc[t][nt][3] + bv.y, 0.f);
                *(float2*)(out + (size_t)r1 * 128 + col) = o;
            }
        }
    }
}

// ---------------- head: gather rows, dot with lin_w, sigmoid ----------------
__global__ void final_kernel(const int* __restrict__ mu, const int* __restrict__ ms,
                             const float* __restrict__ lw, const float* __restrict__ lb,
                             float* __restrict__ out) {
    int t = blockIdx.x * blockDim.x + threadIdx.x;
    int m = t >> 5, lane = t & 31;
    if (m >= NMx) return;
    int iu = mu[m], is_ = ms[m];
    float4 a  = ((const float4*)g_u2)[(size_t)iu  * 32 + lane];
    float4 w  = ((const float4*)lw)[lane];
    float s = a.x * w.x + a.y * w.y + a.z * w.z + a.w * w.w;
    float4 b  = ((const float4*)g_s2)[(size_t)is_ * 32 + lane];
    float4 w2 = ((const float4*)lw)[32 + lane];
    s += b.x * w2.x + b.y * w2.y + b.z * w2.z + b.w * w2.w;
#pragma unroll
    for (int o = 16; o; o >>= 1) s += __shfl_down_sync(0xffffffffu, s, o);
    if (lane == 0) out[m] = 1.f / (1.f + expf(-(s + lb[0])));
}

// ---------------- launcher ----------------
extern "C" void kernel_launch(void* const* d_in, const int* in_sizes, int n_in,
                              void* d_out, int out_size) {
    (void)in_sizes; (void)n_in; (void)out_size;
    const float* x_user_feat   = (const float*)d_in[0];
    const float* x_seller_feat = (const float*)d_in[1];
    const int*   x1            = (const int*)  d_in[2];
    const int*   src_user      = (const int*)  d_in[3];
    const int*   dst_seller    = (const int*)  d_in[4];
    const int*   src_seller    = (const int*)  d_in[5];
    const int*   dst_user      = (const int*)  d_in[6];
    const int*   mask_user     = (const int*)  d_in[7];
    const int*   mask_seller   = (const int*)  d_in[8];
    const float* age_emb       = (const float*)d_in[9];
    const float* gen_emb       = (const float*)d_in[10];
    const float* W1ul = (const float*)d_in[11];
    const float* W1ur = (const float*)d_in[12];
    const float* b1u  = (const float*)d_in[13];
    const float* W1sl = (const float*)d_in[14];
    const float* W1sr = (const float*)d_in[15];
    const float* b1s  = (const float*)d_in[16];
    const float* W2ul = (const float*)d_in[17];
    const float* W2ur = (const float*)d_in[18];
    const float* b2u  = (const float*)d_in[19];
    const float* W2sl = (const float*)d_in[20];
    const float* W2sr = (const float*)d_in[21];
    const float* b2s  = (const float*)d_in[22];
    const float* lin_w = (const float*)d_in[23];
    const float* lin_b = (const float*)d_in[24];
    float* out = (float*)d_out;

    float *xu, *aggU, *aggS, *u1, *s1, *u2, *s2;
    int *cntU, *cntS;
    uint32_t* Bimg;
    cudaGetSymbolAddress((void**)&xu,   g_xu);
    cudaGetSymbolAddress((void**)&aggU, g_aggU);
    cudaGetSymbolAddress((void**)&aggS, g_aggS);
    cudaGetSymbolAddress((void**)&u1,   g_u1);
    cudaGetSymbolAddress((void**)&s1,   g_s1);
    cudaGetSymbolAddress((void**)&u2,   g_u2);
    cudaGetSymbolAddress((void**)&s2,   g_s2);
    cudaGetSymbolAddress((void**)&cntU, g_cntU);
    cudaGetSymbolAddress((void**)&cntS, g_cntS);
    cudaGetSymbolAddress((void**)&Bimg, g_Bimg);

    const int SM192 = 128 * (192 + 4) * 4;   // 100352
    const int SM256 = 128 * (256 + 4) * 4;   // 133120
    cudaFuncSetAttribute(gemm_mma<64,128>,  cudaFuncAttributeMaxDynamicSharedMemorySize, SM192);
    cudaFuncSetAttribute(gemm_mma<128,64>,  cudaFuncAttributeMaxDynamicSharedMemorySize, SM192);
    cudaFuncSetAttribute(gemm_mma<128,128>, cudaFuncAttributeMaxDynamicSharedMemorySize, SM256);

    const int T = 256;

    // zero agg buffers + counts
    zero_kernel<<<(NUx*32 + T - 1) / T, T>>>((float4*)aggU, (long long)NUx * 32);
    zero_kernel<<<(NSx*32 + T - 1) / T, T>>>((float4*)aggS, (long long)NSx * 32);
    zero_kernel<<<(NUx/4  + T - 1) / T, T>>>((float4*)cntU, NUx / 4);
    zero_kernel<<<(NSx/4  + T - 1) / T, T>>>((float4*)cntS, NSx / 4);

    // build user input features + tf32 fragment weight images
    build_xu_kernel<<<(NUx*32 + T - 1) / T, T>>>(x_user_feat, x1, age_emb, gen_emb);
    build_B_kernel<<<(192*128 + T - 1) / T, T>>>(W1ul, W1ur,  64, 192, Bimg + 0*32768);
    build_B_kernel<<<(192*128 + T - 1) / T, T>>>(W1sl, W1sr, 128, 192, Bimg + 1*32768);
    build_B_kernel<<<(256*128 + T - 1) / T, T>>>(W2ul, W2ur, 128, 256, Bimg + 2*32768);
    build_B_kernel<<<(256*128 + T - 1) / T, T>>>(W2sl, W2sr, 128, 256, Bimg + 3*32768);

    // layer 1 aggregation (+fused degree counts)
    scatter_warp<16,true><<<(int)(((long long)NEx*16 + T - 1) / T), T>>>(x_seller_feat, src_seller, dst_user,   aggU, cntU);
    scatter_warp<32,true><<<(int)(((long long)NEx*32 + T - 1) / T), T>>>(xu,            src_user,   dst_seller, aggS, cntS);

    // layer 1 dense (tf32 mma.sync)
    gemm_mma<64,128><<<(NUx + 127) / 128, 256, SM192>>>(aggU, cntU, xu,            Bimg + 0*32768, b1u, u1, NUx);
    gemm_mma<128,64><<<(NSx + 127) / 128, 256, SM192>>>(aggS, cntS, x_seller_feat, Bimg + 1*32768, b1s, s1, NSx);

    // layer 2 aggregation
    zero_kernel<<<(NUx*32 + T - 1) / T, T>>>((float4*)aggU, (long long)NUx * 32);
    zero_kernel<<<(NSx*32 + T - 1) / T, T>>>((float4*)aggS, (long long)NSx * 32);
    scatter_warp<32,false><<<(int)(((long long)NEx*32 + T - 1) / T), T>>>(s1, src_seller, dst_user,   aggU, nullptr);
    scatter_warp<32,false><<<(int)(((long long)NEx*32 + T - 1) / T), T>>>(u1, src_user,   dst_seller, aggS, nullptr);

    // layer 2 dense (tf32 mma.sync)
    gemm_mma<128,128><<<(NUx + 127) / 128, 256, SM256>>>(aggU, cntU, u1, Bimg + 2*32768, b2u, u2, NUx);
    gemm_mma<128,128><<<(NSx + 127) / 128, 256, SM256>>>(aggS, cntS, s1, Bimg + 3*32768, b2s, s2, NSx);

    // head
    final_kernel<<<(NMx*32 + T - 1) / T, T>>>(mask_user, mask_seller, lin_w, lin_b, out);
}

// round 5
// speedup vs baseline: 2.7990x; 1.1168x over previous
#include <cuda_runtime.h>
#include <math.h>
#include <stdint.h>

#define NUx 200000
#define NSx 50000
#define NEx 1000000
#define NMx 100000
#define Hx  128

// ---------------- scratch (device globals; no allocation allowed) ----------------
__device__ float g_xu  [(size_t)NUx * Hx];
__device__ float g_aggU[(size_t)NUx * Hx];
__device__ float g_aggS[(size_t)NSx * Hx];
__device__ float g_u1  [(size_t)NUx * Hx];
__device__ float g_s1  [(size_t)NSx * Hx];
__device__ float g_partU[NMx];            // fused dot of u2[mask] with lin_w[0:128]
__device__ float g_dotS [NSx];            // fused dot of s2 with lin_w[128:256]
__device__ int   g_cntU[NUx];
__device__ int   g_cntS[NSx];
__device__ uint32_t g_Bimg[4 * 32768];    // 4 tf32 weight images in mma fragment layout

__device__ __forceinline__ uint32_t f2tf32(float x) {
    uint32_t r;
    asm("cvt.rna.tf32.f32 %0, %1;" : "=r"(r) : "f"(x));
    return r;
}

// ---------------- zero fill ----------------
__global__ void zero_kernel(float4* __restrict__ p, long long n4) {
    long long i = (long long)blockIdx.x * blockDim.x + threadIdx.x;
    if (i < n4) p[i] = make_float4(0.f, 0.f, 0.f, 0.f);
}

// ---------------- build x_u = [age_emb | gen_emb | feat] ----------------
__global__ void build_xu_kernel(const float* __restrict__ feat,
                                const int*   __restrict__ x1,
                                const float* __restrict__ age_emb,
                                const float* __restrict__ gen_emb) {
    int tid = blockIdx.x * blockDim.x + threadIdx.x;
    if (tid >= NUx * 32) return;
    int r = tid >> 5, c = tid & 31;
    float4 v;
    if (c < 8) {
        int a = x1[2 * r];
        v = ((const float4*)age_emb)[a * 8 + c];
    } else if (c < 16) {
        int g = x1[2 * r + 1];
        v = ((const float4*)gen_emb)[g * 8 + (c - 8)];
    } else {
        v = ((const float4*)feat)[(size_t)r * 16 + (c - 16)];
    }
    ((float4*)g_xu)[(size_t)r * 32 + c] = v;
}

// ---------------- build tf32 weight image in m16n8k8 B-fragment layout ----------------
__global__ void build_B_kernel(const float* __restrict__ Wl, const float* __restrict__ Wr,
                               int FA, int K, uint32_t* __restrict__ img) {
    int tid = blockIdx.x * blockDim.x + threadIdx.x;
    if (tid >= K * 128) return;
    int k = tid >> 7, n = tid & 127;
    float v = (k < FA) ? Wl[k * 128 + n] : Wr[(k - FA) * 128 + n];
    int ntile = n >> 3;
    int lane  = ((n & 7) << 2) | (k & 3);
    int reg   = (k >> 2) & 1;
    int kstep = k >> 3;
    img[((ntile * (K >> 3) + kstep) * 32 + lane) * 2 + reg] = f2tf32(v);
}

// ---------------- edge scatter-add (warp-cooperative, vector red) ----------------
template<int LPE, bool COUNT>
__global__ void __launch_bounds__(256)
scatter_warp(const float* __restrict__ feat,
             const int*   __restrict__ src,
             const int*   __restrict__ dst,
             float*       __restrict__ agg,
             int*         __restrict__ cnt) {
    long long tid = (long long)blockIdx.x * blockDim.x + threadIdx.x;
    int e = (int)(tid >> (LPE == 32 ? 5 : 4));
    if (e >= NEx) return;
    int lane = threadIdx.x & 31;
    int sub = lane & (LPE - 1);
    int leader = lane & ~(LPE - 1);
    int s = 0, d = 0;
    if (sub == 0) { s = src[e]; d = dst[e]; }
    s = __shfl_sync(0xffffffffu, s, leader);
    d = __shfl_sync(0xffffffffu, d, leader);
    float4 v = ((const float4*)feat)[(size_t)s * LPE + sub];
    float* o = agg + (size_t)d * (LPE * 4) + sub * 4;
    asm volatile("red.global.add.v4.f32 [%0], {%1,%2,%3,%4};"
                 :: "l"(o), "f"(v.x), "f"(v.y), "f"(v.z), "f"(v.w)
                 : "memory");
    if (COUNT && sub == 0) atomicAdd(&cnt[d], 1);
}

// ================= tf32 mma.sync GEMM core (shared between both epilogues) =========
// CTA = 128 rows x 128 cols. 8 warps: (wid&3)=M strip of 32 rows, (wid>>2)=N half.
// DOT=false: writes full relu(out) matrix. DOT=true: fuses bias+relu+dot(lin_w seg),
// writes one scalar per row. GATHER=true: A rows gathered via mask[].
template<int FA, int FB, bool DOT, bool GATHER>
__global__ void __launch_bounds__(256, 1)
gemm_mma(const float* __restrict__ agg, const int* __restrict__ cnt,
         const float* __restrict__ xr, const uint32_t* __restrict__ Bfrag,
         const float* __restrict__ bias, const float* __restrict__ lw,
         float* __restrict__ out, int Nrows, const int* __restrict__ mask)
{
    constexpr int K   = FA + FB;
    constexpr int KS  = K / 8;
    constexpr int LDA = K + 4;

    extern __shared__ uint32_t sA[];   // [128][LDA] tf32 bits (+128 floats partials if DOT)
    float* part = (float*)(sA + 128 * LDA);
    const int tid  = threadIdx.x;
    const int wid  = tid >> 5;
    const int lane = tid & 31;
    const int tile0 = blockIdx.x * 128;

    // ---- stage A (scale by 1/deg on agg part, tf32-convert) ----
    {
        const int row  = tid >> 1;
        const int half = tid & 1;
        int idx = tile0 + row; if (idx >= Nrows) idx = Nrows - 1;
        int grow = GATHER ? mask[idx] : idx;
        int c = cnt[grow];
        const float inv = 1.f / (float)(c > 1 ? c : 1);
        const float4* pa = (const float4*)(agg + (size_t)grow * FA);
        const float4* px = (const float4*)(xr  + (size_t)grow * FB);
#pragma unroll
        for (int j = 0; j < K / 8; j++) {
            int k4 = half * (K / 8) + j;
            int kf = k4 * 4;
            float4 v; float sc;
            if (kf < FA) { v = pa[k4]; sc = inv; }
            else         { v = px[k4 - FA / 4]; sc = 1.f; }
            uint4 t;
            t.x = f2tf32(v.x * sc); t.y = f2tf32(v.y * sc);
            t.z = f2tf32(v.z * sc); t.w = f2tf32(v.w * sc);
            *(uint4*)(sA + row * LDA + kf) = t;
        }
        if (DOT && tid < 128) part[tid] = 0.f;
    }
    __syncthreads();

    const int wm = wid & 3;
    const int wn = wid >> 2;
    const int lr = lane >> 2;
    const int lc = lane & 3;

    float acc[2][8][4];
#pragma unroll
    for (int t = 0; t < 2; t++)
#pragma unroll
        for (int nt = 0; nt < 8; nt++)
#pragma unroll
            for (int q = 0; q < 4; q++) acc[t][nt][q] = 0.f;

    const uint32_t* Ab = sA + (wm * 32 + lr) * LDA + lc;
    const uint2* Bp = (const uint2*)Bfrag + (size_t)(wn * 8) * KS * 32 + lane;

    uint2 bc[8], bn[8];
#pragma unroll
    for (int nt = 0; nt < 8; nt++) bc[nt] = Bp[nt * KS * 32];

#pragma unroll
    for (int ks = 0; ks < KS; ks++) {
        if (ks + 1 < KS) {
#pragma unroll
            for (int nt = 0; nt < 8; nt++) bn[nt] = Bp[nt * KS * 32 + (ks + 1) * 32];
        }
        uint32_t a[2][4];
#pragma unroll
        for (int t = 0; t < 2; t++) {
            const uint32_t* p = Ab + t * 16 * LDA + ks * 8;
            a[t][0] = p[0];
            a[t][1] = p[8 * LDA];
            a[t][2] = p[4];
            a[t][3] = p[8 * LDA + 4];
        }
#pragma unroll
        for (int t = 0; t < 2; t++)
#pragma unroll
            for (int nt = 0; nt < 8; nt++) {
                asm volatile(
                    "mma.sync.aligned.m16n8k8.row.col.f32.tf32.tf32.f32 "
                    "{%0,%1,%2,%3}, {%4,%5,%6,%7}, {%8,%9}, {%0,%1,%2,%3};"
                    : "+f"(acc[t][nt][0]), "+f"(acc[t][nt][1]),
                      "+f"(acc[t][nt][2]), "+f"(acc[t][nt][3])
                    : "r"(a[t][0]), "r"(a[t][1]), "r"(a[t][2]), "r"(a[t][3]),
                      "r"(bc[nt].x), "r"(bc[nt].y));
            }
#pragma unroll
        for (int nt = 0; nt < 8; nt++) bc[nt] = bn[nt];
    }

    if (!DOT) {
        // ---- epilogue A: bias + relu, full matrix store ----
#pragma unroll
        for (int nt = 0; nt < 8; nt++) {
            const int col = wn * 64 + nt * 8 + lc * 2;
            const float2 bv = *(const float2*)(bias + col);
#pragma unroll
            for (int t = 0; t < 2; t++) {
                int r0 = tile0 + wm * 32 + t * 16 + lr;
                if (r0 < Nrows) {
                    float2 o;
                    o.x = fmaxf(acc[t][nt][0] + bv.x, 0.f);
                    o.y = fmaxf(acc[t][nt][1] + bv.y, 0.f);
                    *(float2*)(out + (size_t)r0 * 128 + col) = o;
                }
                int r1 = r0 + 8;
                if (r1 < Nrows) {
                    float2 o;
                    o.x = fmaxf(acc[t][nt][2] + bv.x, 0.f);
                    o.y = fmaxf(acc[t][nt][3] + bv.y, 0.f);
                    *(float2*)(out + (size_t)r1 * 128 + col) = o;
                }
            }
        }
    } else {
        // ---- epilogue B: bias + relu + dot(lin_w segment) -> scalar per row ----
        float p[2][2] = {{0.f, 0.f}, {0.f, 0.f}};   // [t][r0/r1]
#pragma unroll
        for (int nt = 0; nt < 8; nt++) {
            const int col = wn * 64 + nt * 8 + lc * 2;
            const float2 bv = *(const float2*)(bias + col);
            const float2 wv = *(const float2*)(lw + col);
#pragma unroll
            for (int t = 0; t < 2; t++) {
                p[t][0] += fmaxf(acc[t][nt][0] + bv.x, 0.f) * wv.x
                         + fmaxf(acc[t][nt][1] + bv.y, 0.f) * wv.y;
                p[t][1] += fmaxf(acc[t][nt][2] + bv.x, 0.f) * wv.x
                         + fmaxf(acc[t][nt][3] + bv.y, 0.f) * wv.y;
            }
        }
#pragma unroll
        for (int t = 0; t < 2; t++)
#pragma unroll
            for (int h = 0; h < 2; h++) {
                p[t][h] += __shfl_xor_sync(0xffffffffu, p[t][h], 1);
                p[t][h] += __shfl_xor_sync(0xffffffffu, p[t][h], 2);
            }
        if (lc == 0) {
#pragma unroll
            for (int t = 0; t < 2; t++) {
                atomicAdd(&part[wm * 32 + t * 16 + lr],     p[t][0]);
                atomicAdd(&part[wm * 32 + t * 16 + lr + 8], p[t][1]);
            }
        }
        __syncthreads();
        if (tid < 128) {
            int idx = tile0 + tid;
            if (idx < Nrows) out[idx] = part[tid];
        }
    }
}

// ---------------- head: partials -> sigmoid ----------------
__global__ void final_kernel(const int* __restrict__ ms,
                             const float* __restrict__ partU,
                             const float* __restrict__ dotS,
                             const float* __restrict__ lb,
                             float* __restrict__ out) {
    int m = blockIdx.x * blockDim.x + threadIdx.x;
    if (m >= NMx) return;
    float s = partU[m] + dotS[ms[m]] + lb[0];
    out[m] = 1.f / (1.f + expf(-s));
}

// ---------------- launcher ----------------
extern "C" void kernel_launch(void* const* d_in, const int* in_sizes, int n_in,
                              void* d_out, int out_size) {
    (void)in_sizes; (void)n_in; (void)out_size;
    const float* x_user_feat   = (const float*)d_in[0];
    const float* x_seller_feat = (const float*)d_in[1];
    const int*   x1            = (const int*)  d_in[2];
    const int*   src_user      = (const int*)  d_in[3];
    const int*   dst_seller    = (const int*)  d_in[4];
    const int*   src_seller    = (const int*)  d_in[5];
    const int*   dst_user      = (const int*)  d_in[6];
    const int*   mask_user     = (const int*)  d_in[7];
    const int*   mask_seller   = (const int*)  d_in[8];
    const float* age_emb       = (const float*)d_in[9];
    const float* gen_emb       = (const float*)d_in[10];
    const float* W1ul = (const float*)d_in[11];
    const float* W1ur = (const float*)d_in[12];
    const float* b1u  = (const float*)d_in[13];
    const float* W1sl = (const float*)d_in[14];
    const float* W1sr = (const float*)d_in[15];
    const float* b1s  = (const float*)d_in[16];
    const float* W2ul = (const float*)d_in[17];
    const float* W2ur = (const float*)d_in[18];
    const float* b2u  = (const float*)d_in[19];
    const float* W2sl = (const float*)d_in[20];
    const float* W2sr = (const float*)d_in[21];
    const float* b2s  = (const float*)d_in[22];
    const float* lin_w = (const float*)d_in[23];
    const float* lin_b = (const float*)d_in[24];
    float* out = (float*)d_out;

    float *xu, *aggU, *aggS, *u1, *s1, *partU, *dotS;
    int *cntU, *cntS;
    uint32_t* Bimg;
    cudaGetSymbolAddress((void**)&xu,    g_xu);
    cudaGetSymbolAddress((void**)&aggU,  g_aggU);
    cudaGetSymbolAddress((void**)&aggS,  g_aggS);
    cudaGetSymbolAddress((void**)&u1,    g_u1);
    cudaGetSymbolAddress((void**)&s1,    g_s1);
    cudaGetSymbolAddress((void**)&partU, g_partU);
    cudaGetSymbolAddress((void**)&dotS,  g_dotS);
    cudaGetSymbolAddress((void**)&cntU,  g_cntU);
    cudaGetSymbolAddress((void**)&cntS,  g_cntS);
    cudaGetSymbolAddress((void**)&Bimg,  g_Bimg);

    const int SM192 = 128 * (192 + 4) * 4;          // layer-1 kernels
    const int SM256 = 128 * (256 + 4) * 4 + 512;    // layer-2 (+128 dot partials)
    cudaFuncSetAttribute((const void*)gemm_mma<64,128,false,false>,
                         cudaFuncAttributeMaxDynamicSharedMemorySize, SM192);
    cudaFuncSetAttribute((const void*)gemm_mma<128,64,false,false>,
                         cudaFuncAttributeMaxDynamicSharedMemorySize, SM192);
    cudaFuncSetAttribute((const void*)gemm_mma<128,128,true,true>,
                         cudaFuncAttributeMaxDynamicSharedMemorySize, SM256);
    cudaFuncSetAttribute((const void*)gemm_mma<128,128,true,false>,
                         cudaFuncAttributeMaxDynamicSharedMemorySize, SM256);

    const int T = 256;

    // zero agg buffers + counts
    zero_kernel<<<(NUx*32 + T - 1) / T, T>>>((float4*)aggU, (long long)NUx * 32);
    zero_kernel<<<(NSx*32 + T - 1) / T, T>>>((float4*)aggS, (long long)NSx * 32);
    zero_kernel<<<(NUx/4  + T - 1) / T, T>>>((float4*)cntU, NUx / 4);
    zero_kernel<<<(NSx/4  + T - 1) / T, T>>>((float4*)cntS, NSx / 4);

    // build user input features + tf32 fragment weight images
    build_xu_kernel<<<(NUx*32 + T - 1) / T, T>>>(x_user_feat, x1, age_emb, gen_emb);
    build_B_kernel<<<(192*128 + T - 1) / T, T>>>(W1ul, W1ur,  64, 192, Bimg + 0*32768);
    build_B_kernel<<<(192*128 + T - 1) / T, T>>>(W1sl, W1sr, 128, 192, Bimg + 1*32768);
    build_B_kernel<<<(256*128 + T - 1) / T, T>>>(W2ul, W2ur, 128, 256, Bimg + 2*32768);
    build_B_kernel<<<(256*128 + T - 1) / T, T>>>(W2sl, W2sr, 128, 256, Bimg + 3*32768);

    // layer 1 aggregation (+fused degree counts)
    scatter_warp<16,true><<<(int)(((long long)NEx*16 + T - 1) / T), T>>>(x_seller_feat, src_seller, dst_user,   aggU, cntU);
    scatter_warp<32,true><<<(int)(((long long)NEx*32 + T - 1) / T), T>>>(xu,            src_user,   dst_seller, aggS, cntS);

    // layer 1 dense (tf32 mma.sync, full outputs)
    gemm_mma<64,128,false,false><<<(NUx + 127) / 128, 256, SM192>>>(aggU, cntU, xu,            Bimg + 0*32768, b1u, nullptr, u1, NUx, nullptr);
    gemm_mma<128,64,false,false><<<(NSx + 127) / 128, 256, SM192>>>(aggS, cntS, x_seller_feat, Bimg + 1*32768, b1s, nullptr, s1, NSx, nullptr);

    // layer 2 aggregation
    zero_kernel<<<(NUx*32 + T - 1) / T, T>>>((float4*)aggU, (long long)NUx * 32);
    zero_kernel<<<(NSx*32 + T - 1) / T, T>>>((float4*)aggS, (long long)NSx * 32);
    scatter_warp<32,false><<<(int)(((long long)NEx*32 + T - 1) / T), T>>>(s1, src_seller, dst_user,   aggU, nullptr);
    scatter_warp<32,false><<<(int)(((long long)NEx*32 + T - 1) / T), T>>>(u1, src_user,   dst_seller, aggS, nullptr);

    // layer 2 dense, fused head-dot epilogues:
    //  users: gathered by mask (100k rows), dot with lin_w[0:128]
    //  sellers: all 50k rows, dot with lin_w[128:256]
    gemm_mma<128,128,true,true ><<<(NMx + 127) / 128, 256, SM256>>>(aggU, cntU, u1, Bimg + 2*32768, b2u, lin_w,       partU, NMx, mask_user);
    gemm_mma<128,128,true,false><<<(NSx + 127) / 128, 256, SM256>>>(aggS, cntS, s1, Bimg + 3*32768, b2s, lin_w + 128, dotS,  NSx, nullptr);

    // head
    final_kernel<<<(NMx + T - 1) / T, T>>>(mask_seller, partU, dotS, lin_b, out);
}

// round 6
// speedup vs baseline: 2.8272x; 1.0101x over previous
#include <cuda_runtime.h>
#include <math.h>
#include <stdint.h>

#define NUx 200000
#define NSx 50000
#define NEx 1000000
#define NMx 100000
#define Hx  128

// ---------------- scratch (device globals; no allocation allowed) ----------------
__device__ float g_xu  [(size_t)NUx * Hx];
__device__ float g_aggU[(size_t)NUx * Hx];
__device__ float g_aggS[(size_t)NSx * Hx];
__device__ float g_u1  [(size_t)NUx * Hx];
__device__ float g_s1  [(size_t)NSx * Hx];
__device__ float g_partU[NMx];            // fused dot of u2[mask] with lin_w[0:128]
__device__ float g_dotS [NSx];            // fused dot of s2 with lin_w[128:256]
__device__ int   g_cntU[NUx];
__device__ int   g_cntS[NSx];
__device__ unsigned char g_flagU[NUx];    // user appears in mask_user
__device__ unsigned char g_flagS[NSx];    // seller appears in mask_seller
__device__ uint32_t g_Bimg[4 * 32768];    // 4 tf32 weight images in mma fragment layout

__device__ __forceinline__ uint32_t f2tf32(float x) {
    uint32_t r;
    asm("cvt.rna.tf32.f32 %0, %1;" : "=r"(r) : "f"(x));
    return r;
}

// ---------------- zero fill ----------------
__global__ void zero_kernel(float4* __restrict__ p, long long n4) {
    long long i = (long long)blockIdx.x * blockDim.x + threadIdx.x;
    if (i < n4) p[i] = make_float4(0.f, 0.f, 0.f, 0.f);
}

// ---------------- set mask-membership flags ----------------
__global__ void flag_kernel(const int* __restrict__ mu, const int* __restrict__ ms,
                            unsigned char* __restrict__ fu, unsigned char* __restrict__ fs) {
    int m = blockIdx.x * blockDim.x + threadIdx.x;
    if (m >= NMx) return;
    fu[mu[m]] = 1;
    fs[ms[m]] = 1;
}

// ---------------- build x_u = [age_emb | gen_emb | feat] ----------------
__global__ void build_xu_kernel(const float* __restrict__ feat,
                                const int*   __restrict__ x1,
                                const float* __restrict__ age_emb,
                                const float* __restrict__ gen_emb) {
    int tid = blockIdx.x * blockDim.x + threadIdx.x;
    if (tid >= NUx * 32) return;
    int r = tid >> 5, c = tid & 31;
    float4 v;
    if (c < 8) {
        int a = x1[2 * r];
        v = ((const float4*)age_emb)[a * 8 + c];
    } else if (c < 16) {
        int g = x1[2 * r + 1];
        v = ((const float4*)gen_emb)[g * 8 + (c - 8)];
    } else {
        v = ((const float4*)feat)[(size_t)r * 16 + (c - 16)];
    }
    ((float4*)g_xu)[(size_t)r * 32 + c] = v;
}

// ---------------- build tf32 weight image in m16n8k8 B-fragment layout ----------------
__global__ void build_B_kernel(const float* __restrict__ Wl, const float* __restrict__ Wr,
                               int FA, int K, uint32_t* __restrict__ img) {
    int tid = blockIdx.x * blockDim.x + threadIdx.x;
    if (tid >= K * 128) return;
    int k = tid >> 7, n = tid & 127;
    float v = (k < FA) ? Wl[k * 128 + n] : Wr[(k - FA) * 128 + n];
    int ntile = n >> 3;
    int lane  = ((n & 7) << 2) | (k & 3);
    int reg   = (k >> 2) & 1;
    int kstep = k >> 3;
    img[((ntile * (K >> 3) + kstep) * 32 + lane) * 2 + reg] = f2tf32(v);
}

// ---------------- edge scatter-add (warp-cooperative, vector red) ----------------
// FLAG: skip edges whose destination is never read downstream.
template<int LPE, bool COUNT, bool FLAG>
__global__ void __launch_bounds__(256)
scatter_warp(const float* __restrict__ feat,
             const int*   __restrict__ src,
             const int*   __restrict__ dst,
             float*       __restrict__ agg,
             int*         __restrict__ cnt,
             const unsigned char* __restrict__ flag) {
    long long tid = (long long)blockIdx.x * blockDim.x + threadIdx.x;
    int e = (int)(tid >> (LPE == 32 ? 5 : 4));
    if (e >= NEx) return;
    int lane = threadIdx.x & 31;
    int sub = lane & (LPE - 1);
    int leader = lane & ~(LPE - 1);
    int s = 0, d = 0, f = 1;
    if (sub == 0) {
        s = src[e]; d = dst[e];
        if (FLAG) f = flag[d];
    }
    s = __shfl_sync(0xffffffffu, s, leader);
    d = __shfl_sync(0xffffffffu, d, leader);
    if (FLAG) {
        f = __shfl_sync(0xffffffffu, f, leader);
        if (!f) return;
    }
    float4 v = ((const float4*)feat)[(size_t)s * LPE + sub];
    float* o = agg + (size_t)d * (LPE * 4) + sub * 4;
    asm volatile("red.global.add.v4.f32 [%0], {%1,%2,%3,%4};"
                 :: "l"(o), "f"(v.x), "f"(v.y), "f"(v.z), "f"(v.w)
                 : "memory");
    if (COUNT && sub == 0) atomicAdd(&cnt[d], 1);
}

// ================= tf32 mma.sync GEMM core (shared between both epilogues) =========
// CTA = 128 rows x 128 cols. 8 warps: (wid&3)=M strip of 32 rows, (wid>>2)=N half.
// DOT=false: writes full relu(out) matrix. DOT=true: fuses bias+relu+dot(lin_w seg),
// writes one scalar per row. GATHER=true: A rows gathered via mask[].
template<int FA, int FB, bool DOT, bool GATHER>
__global__ void __launch_bounds__(256, 1)
gemm_mma(const float* __restrict__ agg, const int* __restrict__ cnt,
         const float* __restrict__ xr, const uint32_t* __restrict__ Bfrag,
         const float* __restrict__ bias, const float* __restrict__ lw,
         float* __restrict__ out, int Nrows, const int* __restrict__ mask)
{
    constexpr int K   = FA + FB;
    constexpr int KS  = K / 8;
    constexpr int LDA = K + 4;

    extern __shared__ uint32_t sA[];   // [128][LDA] tf32 bits (+128 floats partials if DOT)
    float* part = (float*)(sA + 128 * LDA);
    const int tid  = threadIdx.x;
    const int wid  = tid >> 5;
    const int lane = tid & 31;
    const int tile0 = blockIdx.x * 128;

    // ---- stage A (scale by 1/deg on agg part, tf32-convert) ----
    {
        const int row  = tid >> 1;
        const int half = tid & 1;
        int idx = tile0 + row; if (idx >= Nrows) idx = Nrows - 1;
        int grow = GATHER ? mask[idx] : idx;
        int c = cnt[grow];
        const float inv = 1.f / (float)(c > 1 ? c : 1);
        const float4* pa = (const float4*)(agg + (size_t)grow * FA);
        const float4* px = (const float4*)(xr  + (size_t)grow * FB);
#pragma unroll
        for (int j = 0; j < K / 8; j++) {
            int k4 = half * (K / 8) + j;
            int kf = k4 * 4;
            float4 v; float sc;
            if (kf < FA) { v = pa[k4]; sc = inv; }
            else         { v = px[k4 - FA / 4]; sc = 1.f; }
            uint4 t;
            t.x = f2tf32(v.x * sc); t.y = f2tf32(v.y * sc);
            t.z = f2tf32(v.z * sc); t.w = f2tf32(v.w * sc);
            *(uint4*)(sA + row * LDA + kf) = t;
        }
        if (DOT && tid < 128) part[tid] = 0.f;
    }
    __syncthreads();

    const int wm = wid & 3;
    const int wn = wid >> 2;
    const int lr = lane >> 2;
    const int lc = lane & 3;

    float acc[2][8][4];
#pragma unroll
    for (int t = 0; t < 2; t++)
#pragma unroll
        for (int nt = 0; nt < 8; nt++)
#pragma unroll
            for (int q = 0; q < 4; q++) acc[t][nt][q] = 0.f;

    const uint32_t* Ab = sA + (wm * 32 + lr) * LDA + lc;
    const uint2* Bp = (const uint2*)Bfrag + (size_t)(wn * 8) * KS * 32 + lane;

    uint2 bc[8], bn[8];
#pragma unroll
    for (int nt = 0; nt < 8; nt++) bc[nt] = Bp[nt * KS * 32];

#pragma unroll
    for (int ks = 0; ks < KS; ks++) {
        if (ks + 1 < KS) {
#pragma unroll
            for (int nt = 0; nt < 8; nt++) bn[nt] = Bp[nt * KS * 32 + (ks + 1) * 32];
        }
        uint32_t a[2][4];
#pragma unroll
        for (int t = 0; t < 2; t++) {
            const uint32_t* p = Ab + t * 16 * LDA + ks * 8;
            a[t][0] = p[0];
            a[t][1] = p[8 * LDA];
            a[t][2] = p[4];
            a[t][3] = p[8 * LDA + 4];
        }
#pragma unroll
        for (int t = 0; t < 2; t++)
#pragma unroll
            for (int nt = 0; nt < 8; nt++) {
                asm volatile(
                    "mma.sync.aligned.m16n8k8.row.col.f32.tf32.tf32.f32 "
                    "{%0,%1,%2,%3}, {%4,%5,%6,%7}, {%8,%9}, {%0,%1,%2,%3};"
                    : "+f"(acc[t][nt][0]), "+f"(acc[t][nt][1]),
                      "+f"(acc[t][nt][2]), "+f"(acc[t][nt][3])
                    : "r"(a[t][0]), "r"(a[t][1]), "r"(a[t][2]), "r"(a[t][3]),
                      "r"(bc[nt].x), "r"(bc[nt].y));
            }
#pragma unroll
        for (int nt = 0; nt < 8; nt++) bc[nt] = bn[nt];
    }

    if (!DOT) {
        // ---- epilogue A: bias + relu, full matrix store ----
#pragma unroll
        for (int nt = 0; nt < 8; nt++) {
            const int col = wn * 64 + nt * 8 + lc * 2;
            const float2 bv = *(const float2*)(bias + col);
#pragma unroll
            for (int t = 0; t < 2; t++) {
                int r0 = tile0 + wm * 32 + t * 16 + lr;
                if (r0 < Nrows) {
                    float2 o;
                    o.x = fmaxf(acc[t][nt][0] + bv.x, 0.f);
                    o.y = fmaxf(acc[t][nt][1] + bv.y, 0.f);
                    *(float2*)(out + (size_t)r0 * 128 + col) = o;
                }
                int r1 = r0 + 8;
                if (r1 < Nrows) {
                    float2 o;
                    o.x = fmaxf(acc[t][nt][2] + bv.x, 0.f);
                    o.y = fmaxf(acc[t][nt][3] + bv.y, 0.f);
                    *(float2*)(out + (size_t)r1 * 128 + col) = o;
                }
            }
        }
    } else {
        // ---- epilogue B: bias + relu + dot(lin_w segment) -> scalar per row ----
        float p[2][2] = {{0.f, 0.f}, {0.f, 0.f}};   // [t][r0/r1]
#pragma unroll
        for (int nt = 0; nt < 8; nt++) {
            const int col = wn * 64 + nt * 8 + lc * 2;
            const float2 bv = *(const float2*)(bias + col);
            const float2 wv = *(const float2*)(lw + col);
#pragma unroll
            for (int t = 0; t < 2; t++) {
                p[t][0] += fmaxf(acc[t][nt][0] + bv.x, 0.f) * wv.x
                         + fmaxf(acc[t][nt][1] + bv.y, 0.f) * wv.y;
                p[t][1] += fmaxf(acc[t][nt][2] + bv.x, 0.f) * wv.x
                         + fmaxf(acc[t][nt][3] + bv.y, 0.f) * wv.y;
            }
        }
#pragma unroll
        for (int t = 0; t < 2; t++)
#pragma unroll
            for (int h = 0; h < 2; h++) {
                p[t][h] += __shfl_xor_sync(0xffffffffu, p[t][h], 1);
                p[t][h] += __shfl_xor_sync(0xffffffffu, p[t][h], 2);
            }
        if (lc == 0) {
#pragma unroll
            for (int t = 0; t < 2; t++) {
                atomicAdd(&part[wm * 32 + t * 16 + lr],     p[t][0]);
                atomicAdd(&part[wm * 32 + t * 16 + lr + 8], p[t][1]);
            }
        }
        __syncthreads();
        if (tid < 128) {
            int idx = tile0 + tid;
            if (idx < Nrows) out[idx] = part[tid];
        }
    }
}

// ---------------- head: partials -> sigmoid ----------------
__global__ void final_kernel(const int* __restrict__ ms,
                             const float* __restrict__ partU,
                             const float* __restrict__ dotS,
                             const float* __restrict__ lb,
                             float* __restrict__ out) {
    int m = blockIdx.x * blockDim.x + threadIdx.x;
    if (m >= NMx) return;
    float s = partU[m] + dotS[ms[m]] + lb[0];
    out[m] = 1.f / (1.f + expf(-s));
}

// ---------------- launcher ----------------
extern "C" void kernel_launch(void* const* d_in, const int* in_sizes, int n_in,
                              void* d_out, int out_size) {
    (void)in_sizes; (void)n_in; (void)out_size;
    const float* x_user_feat   = (const float*)d_in[0];
    const float* x_seller_feat = (const float*)d_in[1];
    const int*   x1            = (const int*)  d_in[2];
    const int*   src_user      = (const int*)  d_in[3];
    const int*   dst_seller    = (const int*)  d_in[4];
    const int*   src_seller    = (const int*)  d_in[5];
    const int*   dst_user      = (const int*)  d_in[6];
    const int*   mask_user     = (const int*)  d_in[7];
    const int*   mask_seller   = (const int*)  d_in[8];
    const float* age_emb       = (const float*)d_in[9];
    const float* gen_emb       = (const float*)d_in[10];
    const float* W1ul = (const float*)d_in[11];
    const float* W1ur = (const float*)d_in[12];
    const float* b1u  = (const float*)d_in[13];
    const float* W1sl = (const float*)d_in[14];
    const float* W1sr = (const float*)d_in[15];
    const float* b1s  = (const float*)d_in[16];
    const float* W2ul = (const float*)d_in[17];
    const float* W2ur = (const float*)d_in[18];
    const float* b2u  = (const float*)d_in[19];
    const float* W2sl = (const float*)d_in[20];
    const float* W2sr = (const float*)d_in[21];
    const float* b2s  = (const float*)d_in[22];
    const float* lin_w = (const float*)d_in[23];
    const float* lin_b = (const float*)d_in[24];
    float* out = (float*)d_out;

    float *xu, *aggU, *aggS, *u1, *s1, *partU, *dotS;
    int *cntU, *cntS;
    unsigned char *flagU, *flagS;
    uint32_t* Bimg;
    cudaGetSymbolAddress((void**)&xu,    g_xu);
    cudaGetSymbolAddress((void**)&aggU,  g_aggU);
    cudaGetSymbolAddress((void**)&aggS,  g_aggS);
    cudaGetSymbolAddress((void**)&u1,    g_u1);
    cudaGetSymbolAddress((void**)&s1,    g_s1);
    cudaGetSymbolAddress((void**)&partU, g_partU);
    cudaGetSymbolAddress((void**)&dotS,  g_dotS);
    cudaGetSymbolAddress((void**)&cntU,  g_cntU);
    cudaGetSymbolAddress((void**)&cntS,  g_cntS);
    cudaGetSymbolAddress((void**)&flagU, g_flagU);
    cudaGetSymbolAddress((void**)&flagS, g_flagS);
    cudaGetSymbolAddress((void**)&Bimg,  g_Bimg);

    const int SM192 = 128 * (192 + 4) * 4;          // layer-1 kernels
    const int SM256 = 128 * (256 + 4) * 4 + 512;    // layer-2 (+128 dot partials)
    cudaFuncSetAttribute((const void*)gemm_mma<64,128,false,false>,
                         cudaFuncAttributeMaxDynamicSharedMemorySize, SM192);
    cudaFuncSetAttribute((const void*)gemm_mma<128,64,false,false>,
                         cudaFuncAttributeMaxDynamicSharedMemorySize, SM192);
    cudaFuncSetAttribute((const void*)gemm_mma<128,128,true,true>,
                         cudaFuncAttributeMaxDynamicSharedMemorySize, SM256);
    cudaFuncSetAttribute((const void*)gemm_mma<128,128,true,false>,
                         cudaFuncAttributeMaxDynamicSharedMemorySize, SM256);

    const int T = 256;

    // zero agg buffers + counts + flags
    zero_kernel<<<(NUx*32 + T - 1) / T, T>>>((float4*)aggU, (long long)NUx * 32);
    zero_kernel<<<(NSx*32 + T - 1) / T, T>>>((float4*)aggS, (long long)NSx * 32);
    zero_kernel<<<(NUx/4  + T - 1) / T, T>>>((float4*)cntU, NUx / 4);
    zero_kernel<<<(NSx/4  + T - 1) / T, T>>>((float4*)cntS, NSx / 4);
    zero_kernel<<<(NUx/16 + T - 1) / T, T>>>((float4*)flagU, NUx / 16);
    zero_kernel<<<(NSx/16 + T - 1) / T, T>>>((float4*)flagS, NSx / 16);
    flag_kernel<<<(NMx + T - 1) / T, T>>>(mask_user, mask_seller, flagU, flagS);

    // build user input features + tf32 fragment weight images
    build_xu_kernel<<<(NUx*32 + T - 1) / T, T>>>(x_user_feat, x1, age_emb, gen_emb);
    build_B_kernel<<<(192*128 + T - 1) / T, T>>>(W1ul, W1ur,  64, 192, Bimg + 0*32768);
    build_B_kernel<<<(192*128 + T - 1) / T, T>>>(W1sl, W1sr, 128, 192, Bimg + 1*32768);
    build_B_kernel<<<(256*128 + T - 1) / T, T>>>(W2ul, W2ur, 128, 256, Bimg + 2*32768);
    build_B_kernel<<<(256*128 + T - 1) / T, T>>>(W2sl, W2sr, 128, 256, Bimg + 3*32768);

    // layer 1 aggregation (+fused degree counts) — all destinations needed
    scatter_warp<16,true,false><<<(int)(((long long)NEx*16 + T - 1) / T), T>>>(x_seller_feat, src_seller, dst_user,   aggU, cntU, nullptr);
    scatter_warp<32,true,false><<<(int)(((long long)NEx*32 + T - 1) / T), T>>>(xu,            src_user,   dst_seller, aggS, cntS, nullptr);

    // layer 1 dense (tf32 mma.sync, full outputs)
    gemm_mma<64,128,false,false><<<(NUx + 127) / 128, 256, SM192>>>(aggU, cntU, xu,            Bimg + 0*32768, b1u, nullptr, u1, NUx, nullptr);
    gemm_mma<128,64,false,false><<<(NSx + 127) / 128, 256, SM192>>>(aggS, cntS, x_seller_feat, Bimg + 1*32768, b1s, nullptr, s1, NSx, nullptr);

    // layer 2 aggregation — only mask-covered destinations are ever read
    zero_kernel<<<(NUx*32 + T - 1) / T, T>>>((float4*)aggU, (long long)NUx * 32);
    zero_kernel<<<(NSx*32 + T - 1) / T, T>>>((float4*)aggS, (long long)NSx * 32);
    scatter_warp<32,false,true><<<(int)(((long long)NEx*32 + T - 1) / T), T>>>(s1, src_seller, dst_user,   aggU, nullptr, flagU);
    scatter_warp<32,false,true><<<(int)(((long long)NEx*32 + T - 1) / T), T>>>(u1, src_user,   dst_seller, aggS, nullptr, flagS);

    // layer 2 dense, fused head-dot epilogues
    gemm_mma<128,128,true,true ><<<(NMx + 127) / 128, 256, SM256>>>(aggU, cntU, u1, Bimg + 2*32768, b2u, lin_w,       partU, NMx, mask_user);
    gemm_mma<128,128,true,false><<<(NSx + 127) / 128, 256, SM256>>>(aggS, cntS, s1, Bimg + 3*32768, b2s, lin_w + 128, dotS,  NSx, nullptr);

    // head
    final_kernel<<<(NMx + T - 1) / T, T>>>(mask_seller, partU, dotS, lin_b, out);
}

// round 7
// speedup vs baseline: 3.7922x; 1.3413x over previous
#include <cuda_runtime.h>
#include <math.h>
#include <stdint.h>

#define NUx 200000
#define NSx 50000
#define NEx 1000000
#define NMx 100000
#define Hx  128

// ---------------- scratch (device globals; no allocation allowed) ----------------
__device__ float g_aggU[(size_t)NUx * Hx];
__device__ float g_aggS[(size_t)NSx * Hx];
__device__ float g_u1  [(size_t)NUx * Hx];
__device__ float g_s1  [(size_t)NSx * Hx];
__device__ float g_partU[NMx];
__device__ float g_dotS [NSx];
__device__ int   g_cntU[NUx];
__device__ int   g_cntS[NSx];
__device__ unsigned char g_flagU[NUx];
__device__ unsigned char g_flagS[NSx];
__device__ uint32_t g_Bimg[4 * 32768];

__device__ __forceinline__ uint32_t f2tf32(float x) {
    uint32_t r;
    asm("cvt.rna.tf32.f32 %0, %1;" : "=r"(r) : "f"(x));
    return r;
}

// ---------------- zero fill ----------------
__global__ void zero_kernel(float4* __restrict__ p, long long n4) {
    long long i = (long long)blockIdx.x * blockDim.x + threadIdx.x;
    if (i < n4) p[i] = make_float4(0.f, 0.f, 0.f, 0.f);
}

// ---------------- set mask-membership flags ----------------
__global__ void flag_kernel(const int* __restrict__ mu, const int* __restrict__ ms,
                            unsigned char* __restrict__ fu, unsigned char* __restrict__ fs) {
    int m = blockIdx.x * blockDim.x + threadIdx.x;
    if (m >= NMx) return;
    fu[mu[m]] = 1;
    fs[ms[m]] = 1;
}

// ---------------- build tf32 weight image in m16n8k8 B-fragment layout ----------------
__global__ void build_B_kernel(const float* __restrict__ Wl, const float* __restrict__ Wr,
                               int FA, int K, uint32_t* __restrict__ img) {
    int tid = blockIdx.x * blockDim.x + threadIdx.x;
    if (tid >= K * 128) return;
    int k = tid >> 7, n = tid & 127;
    float v = (k < FA) ? Wl[k * 128 + n] : Wr[(k - FA) * 128 + n];
    int ntile = n >> 3;
    int lane  = ((n & 7) << 2) | (k & 3);
    int reg   = (k >> 2) & 1;
    int kstep = k >> 3;
    img[((ntile * (K >> 3) + kstep) * 32 + lane) * 2 + reg] = f2tf32(v);
}

// ---------------- edge scatter-add (LPE lanes/edge, NV float4 per lane) ----------------
// LPL = log2(LPE). Row width F = LPE*NV*4 floats. XU: source row synthesized as
// [age_emb(32) | gen_emb(32) | feat(64)] on the fly from x1 + tables.
template<int LPL, int NV, bool COUNT, bool FLAG, bool XU>
__global__ void __launch_bounds__(256)
scatter_warp(const float* __restrict__ feat,
             const int*   __restrict__ src,
             const int*   __restrict__ dst,
             float*       __restrict__ agg,
             int*         __restrict__ cnt,
             const unsigned char* __restrict__ flag,
             const int*   __restrict__ x1,
             const float* __restrict__ aemb,
             const float* __restrict__ gemb) {
    constexpr int LPE = 1 << LPL;
    constexpr int F4  = LPE * NV;     // float4s per row
    long long gtid = (long long)blockIdx.x * blockDim.x + threadIdx.x;
    int e = (int)(gtid >> LPL);
    if (e >= NEx) return;
    const int lane = threadIdx.x & 31;
    const int sub  = lane & (LPE - 1);
    const int leader = lane & ~(LPE - 1);
    int s = 0, d = 0, f = 1, ax = 0, gx = 0;
    if (sub == 0) {
        s = src[e]; d = dst[e];
        if (FLAG) f = flag[d];
        if (XU) { int2 xx = ((const int2*)x1)[s]; ax = xx.x; gx = xx.y; }
    }
    s = __shfl_sync(0xffffffffu, s, leader);
    d = __shfl_sync(0xffffffffu, d, leader);
    if (FLAG) {
        f = __shfl_sync(0xffffffffu, f, leader);
        if (!f) return;
    }
    if (XU) {
        ax = __shfl_sync(0xffffffffu, ax, leader);
        gx = __shfl_sync(0xffffffffu, gx, leader);
    }
    float4 v[NV];
#pragma unroll
    for (int j = 0; j < NV; j++) {
        int c = j * LPE + sub;
        if (XU) {
            if (c < 8)       v[j] = ((const float4*)aemb)[ax * 8 + c];
            else if (c < 16) v[j] = ((const float4*)gemb)[gx * 8 + (c - 8)];
            else             v[j] = ((const float4*)feat)[(size_t)s * 16 + (c - 16)];
        } else {
            v[j] = ((const float4*)feat)[(size_t)s * F4 + c];
        }
    }
    float* o = agg + (size_t)d * (F4 * 4);
#pragma unroll
    for (int j = 0; j < NV; j++) {
        int c = j * LPE + sub;
        asm volatile("red.global.add.v4.f32 [%0], {%1,%2,%3,%4};"
                     :: "l"(o + c * 4), "f"(v[j].x), "f"(v[j].y), "f"(v[j].z), "f"(v[j].w)
                     : "memory");
    }
    if (COUNT && sub == 0) atomicAdd(&cnt[d], 1);
}

// ================= tf32 mma.sync GEMM core =========
// CTA = 128 rows x 128 cols. DOT: fused bias+relu+dot(lin_w) scalar epilogue.
// GATHER: A rows via mask. XUF: self-features synthesized [age|gen|feat].
template<int FA, int FB, bool DOT, bool GATHER, bool XUF>
__global__ void __launch_bounds__(256, 1)
gemm_mma(const float* __restrict__ agg, const int* __restrict__ cnt,
         const float* __restrict__ xr, const uint32_t* __restrict__ Bfrag,
         const float* __restrict__ bias, const float* __restrict__ lw,
         float* __restrict__ out, int Nrows, const int* __restrict__ mask,
         const int* __restrict__ x1, const float* __restrict__ aemb,
         const float* __restrict__ gemb)
{
    constexpr int K   = FA + FB;
    constexpr int KS  = K / 8;
    constexpr int LDA = K + 4;

    extern __shared__ uint32_t sA[];   // [128][LDA] tf32 bits (+128 floats partials if DOT)
    float* part = (float*)(sA + 128 * LDA);
    const int tid  = threadIdx.x;
    const int wid  = tid >> 5;
    const int lane = tid & 31;
    const int tile0 = blockIdx.x * 128;

    // ---- stage A (scale by 1/deg on agg part, tf32-convert) ----
    {
        const int row  = tid >> 1;
        const int half = tid & 1;
        int idx = tile0 + row; if (idx >= Nrows) idx = Nrows - 1;
        int grow = GATHER ? mask[idx] : idx;
        int c = cnt[grow];
        const float inv = 1.f / (float)(c > 1 ? c : 1);
        const float4* pa = (const float4*)(agg + (size_t)grow * FA);
        const float4* px = (const float4*)(xr  + (size_t)grow * FB);
        int ax = 0, gx = 0;
        if (XUF) { int2 xx = ((const int2*)x1)[grow]; ax = xx.x; gx = xx.y; }
#pragma unroll
        for (int j = 0; j < K / 8; j++) {
            int k4 = half * (K / 8) + j;
            int kf = k4 * 4;
            float4 v; float sc;
            if (kf < FA) { v = pa[k4]; sc = inv; }
            else if (XUF) {
                int cc = k4 - FA / 4;   // chunk within [age|gen|feat] 32-chunk row
                if (cc < 8)       v = ((const float4*)aemb)[ax * 8 + cc];
                else if (cc < 16) v = ((const float4*)gemb)[gx * 8 + (cc - 8)];
                else              v = ((const float4*)xr)[(size_t)grow * 16 + (cc - 16)];
                sc = 1.f;
            } else { v = px[k4 - FA / 4]; sc = 1.f; }
            uint4 t;
            t.x = f2tf32(v.x * sc); t.y = f2tf32(v.y * sc);
            t.z = f2tf32(v.z * sc); t.w = f2tf32(v.w * sc);
            *(uint4*)(sA + row * LDA + kf) = t;
        }
        if (DOT && tid < 128) part[tid] = 0.f;
    }
    __syncthreads();

    const int wm = wid & 3;
    const int wn = wid >> 2;
    const int lr = lane >> 2;
    const int lc = lane & 3;

    float acc[2][8][4];
#pragma unroll
    for (int t = 0; t < 2; t++)
#pragma unroll
        for (int nt = 0; nt < 8; nt++)
#pragma unroll
            for (int q = 0; q < 4; q++) acc[t][nt][q] = 0.f;

    const uint32_t* Ab = sA + (wm * 32 + lr) * LDA + lc;
    const uint2* Bp = (const uint2*)Bfrag + (size_t)(wn * 8) * KS * 32 + lane;

    uint2 bc[8], bn[8];
#pragma unroll
    for (int nt = 0; nt < 8; nt++) bc[nt] = Bp[nt * KS * 32];

#pragma unroll
    for (int ks = 0; ks < KS; ks++) {
        if (ks + 1 < KS) {
#pragma unroll
            for (int nt = 0; nt < 8; nt++) bn[nt] = Bp[nt * KS * 32 + (ks + 1) * 32];
        }
        uint32_t a[2][4];
#pragma unroll
        for (int t = 0; t < 2; t++) {
            const uint32_t* p = Ab + t * 16 * LDA + ks * 8;
            a[t][0] = p[0];
            a[t][1] = p[8 * LDA];
            a[t][2] = p[4];
            a[t][3] = p[8 * LDA + 4];
        }
#pragma unroll
        for (int t = 0; t < 2; t++)
#pragma unroll
            for (int nt = 0; nt < 8; nt++) {
                asm volatile(
                    "mma.sync.aligned.m16n8k8.row.col.f32.tf32.tf32.f32 "
                    "{%0,%1,%2,%3}, {%4,%5,%6,%7}, {%8,%9}, {%0,%1,%2,%3};"
                    : "+f"(acc[t][nt][0]), "+f"(acc[t][nt][1]),
                      "+f"(acc[t][nt][2]), "+f"(acc[t][nt][3])
                    : "r"(a[t][0]), "r"(a[t][1]), "r"(a[t][2]), "r"(a[t][3]),
                      "r"(bc[nt].x), "r"(bc[nt].y));
            }
#pragma unroll
        for (int nt = 0; nt < 8; nt++) bc[nt] = bn[nt];
    }

    if (!DOT) {
#pragma unroll
        for (int nt = 0; nt < 8; nt++) {
            const int col = wn * 64 + nt * 8 + lc * 2;
            const float2 bv = *(const float2*)(bias + col);
#pragma unroll
            for (int t = 0; t < 2; t++) {
                int r0 = tile0 + wm * 32 + t * 16 + lr;
                if (r0 < Nrows) {
                    float2 o;
                    o.x = fmaxf(acc[t][nt][0] + bv.x, 0.f);
                    o.y = fmaxf(acc[t][nt][1] + bv.y, 0.f);
                    *(float2*)(out + (size_t)r0 * 128 + col) = o;
                }
                int r1 = r0 + 8;
                if (r1 < Nrows) {
                    float2 o;
                    o.x = fmaxf(acc[t][nt][2] + bv.x, 0.f);
                    o.y = fmaxf(acc[t][nt][3] + bv.y, 0.f);
                    *(float2*)(out + (size_t)r1 * 128 + col) = o;
                }
            }
        }
    } else {
        float p[2][2] = {{0.f, 0.f}, {0.f, 0.f}};
#pragma unroll
        for (int nt = 0; nt < 8; nt++) {
            const int col = wn * 64 + nt * 8 + lc * 2;
            const float2 bv = *(const float2*)(bias + col);
            const float2 wv = *(const float2*)(lw + col);
#pragma unroll
            for (int t = 0; t < 2; t++) {
                p[t][0] += fmaxf(acc[t][nt][0] + bv.x, 0.f) * wv.x
                         + fmaxf(acc[t][nt][1] + bv.y, 0.f) * wv.y;
                p[t][1] += fmaxf(acc[t][nt][2] + bv.x, 0.f) * wv.x
                         + fmaxf(acc[t][nt][3] + bv.y, 0.f) * wv.y;
            }
        }
#pragma unroll
        for (int t = 0; t < 2; t++)
#pragma unroll
            for (int h = 0; h < 2; h++) {
                p[t][h] += __shfl_xor_sync(0xffffffffu, p[t][h], 1);
                p[t][h] += __shfl_xor_sync(0xffffffffu, p[t][h], 2);
            }
        if (lc == 0) {
#pragma unroll
            for (int t = 0; t < 2; t++) {
                atomicAdd(&part[wm * 32 + t * 16 + lr],     p[t][0]);
                atomicAdd(&part[wm * 32 + t * 16 + lr + 8], p[t][1]);
            }
        }
        __syncthreads();
        if (tid < 128) {
            int idx = tile0 + tid;
            if (idx < Nrows) out[idx] = part[tid];
        }
    }
}

// ---------------- head: partials -> sigmoid ----------------
__global__ void final_kernel(const int* __restrict__ ms,
                             const float* __restrict__ partU,
                             const float* __restrict__ dotS,
                             const float* __restrict__ lb,
                             float* __restrict__ out) {
    int m = blockIdx.x * blockDim.x + threadIdx.x;
    if (m >= NMx) return;
    float s = partU[m] + dotS[ms[m]] + lb[0];
    out[m] = 1.f / (1.f + expf(-s));
}

// ---------------- launcher ----------------
extern "C" void kernel_launch(void* const* d_in, const int* in_sizes, int n_in,
                              void* d_out, int out_size) {
    (void)in_sizes; (void)n_in; (void)out_size;
    const float* x_user_feat   = (const float*)d_in[0];
    const float* x_seller_feat = (const float*)d_in[1];
    const int*   x1            = (const int*)  d_in[2];
    const int*   src_user      = (const int*)  d_in[3];
    const int*   dst_seller    = (const int*)  d_in[4];
    const int*   src_seller    = (const int*)  d_in[5];
    const int*   dst_user      = (const int*)  d_in[6];
    const int*   mask_user     = (const int*)  d_in[7];
    const int*   mask_seller   = (const int*)  d_in[8];
    const float* age_emb       = (const float*)d_in[9];
    const float* gen_emb       = (const float*)d_in[10];
    const float* W1ul = (const float*)d_in[11];
    const float* W1ur = (const float*)d_in[12];
    const float* b1u  = (const float*)d_in[13];
    const float* W1sl = (const float*)d_in[14];
    const float* W1sr = (const float*)d_in[15];
    const float* b1s  = (const float*)d_in[16];
    const float* W2ul = (const float*)d_in[17];
    const float* W2ur = (const float*)d_in[18];
    const float* b2u  = (const float*)d_in[19];
    const float* W2sl = (const float*)d_in[20];
    const float* W2sr = (const float*)d_in[21];
    const float* b2s  = (const float*)d_in[22];
    const float* lin_w = (const float*)d_in[23];
    const float* lin_b = (const float*)d_in[24];
    float* out = (float*)d_out;

    float *aggU, *aggS, *u1, *s1, *partU, *dotS;
    int *cntU, *cntS;
    unsigned char *flagU, *flagS;
    uint32_t* Bimg;
    cudaGetSymbolAddress((void**)&aggU,  g_aggU);
    cudaGetSymbolAddress((void**)&aggS,  g_aggS);
    cudaGetSymbolAddress((void**)&u1,    g_u1);
    cudaGetSymbolAddress((void**)&s1,    g_s1);
    cudaGetSymbolAddress((void**)&partU, g_partU);
    cudaGetSymbolAddress((void**)&dotS,  g_dotS);
    cudaGetSymbolAddress((void**)&cntU,  g_cntU);
    cudaGetSymbolAddress((void**)&cntS,  g_cntS);
    cudaGetSymbolAddress((void**)&flagU, g_flagU);
    cudaGetSymbolAddress((void**)&flagS, g_flagS);
    cudaGetSymbolAddress((void**)&Bimg,  g_Bimg);

    const int SM192 = 128 * (192 + 4) * 4;
    const int SM256 = 128 * (256 + 4) * 4 + 512;
    cudaFuncSetAttribute((const void*)gemm_mma<64,128,false,false,true>,
                         cudaFuncAttributeMaxDynamicSharedMemorySize, SM192);
    cudaFuncSetAttribute((const void*)gemm_mma<128,64,false,false,false>,
                         cudaFuncAttributeMaxDynamicSharedMemorySize, SM192);
    cudaFuncSetAttribute((const void*)gemm_mma<128,128,true,true,false>,
                         cudaFuncAttributeMaxDynamicSharedMemorySize, SM256);
    cudaFuncSetAttribute((const void*)gemm_mma<128,128,true,false,false>,
                         cudaFuncAttributeMaxDynamicSharedMemorySize, SM256);

    const int T = 256;

    // zero agg buffers + counts + flags
    zero_kernel<<<(NUx*32 + T - 1) / T, T>>>((float4*)aggU, (long long)NUx * 32);
    zero_kernel<<<(NSx*32 + T - 1) / T, T>>>((float4*)aggS, (long long)NSx * 32);
    zero_kernel<<<(NUx/4  + T - 1) / T, T>>>((float4*)cntU, NUx / 4);
    zero_kernel<<<(NSx/4  + T - 1) / T, T>>>((float4*)cntS, NSx / 4);
    zero_kernel<<<(NUx/16 + T - 1) / T, T>>>((float4*)flagU, NUx / 16);
    zero_kernel<<<(NSx/16 + T - 1) / T, T>>>((float4*)flagS, NSx / 16);
    flag_kernel<<<(NMx + T - 1) / T, T>>>(mask_user, mask_seller, flagU, flagS);

    // tf32 fragment weight images
    build_B_kernel<<<(192*128 + T - 1) / T, T>>>(W1ul, W1ur,  64, 192, Bimg + 0*32768);
    build_B_kernel<<<(192*128 + T - 1) / T, T>>>(W1sl, W1sr, 128, 192, Bimg + 1*32768);
    build_B_kernel<<<(256*128 + T - 1) / T, T>>>(W2ul, W2ur, 128, 256, Bimg + 2*32768);
    build_B_kernel<<<(256*128 + T - 1) / T, T>>>(W2sl, W2sr, 128, 256, Bimg + 3*32768);

    // layer 1 aggregation (+fused degree counts)
    // sellers feat (64f) -> users : 4 lanes/edge x 4 float4
    scatter_warp<2,4,true,false,false><<<(int)(((long long)NEx*4 + T - 1) / T), T>>>(
        x_seller_feat, src_seller, dst_user, aggU, cntU, nullptr, nullptr, nullptr, nullptr);
    // users [age|gen|feat] (128f, synthesized) -> sellers : 8 lanes/edge x 4 float4
    scatter_warp<3,4,true,false,true><<<(int)(((long long)NEx*8 + T - 1) / T), T>>>(
        x_user_feat, src_user, dst_seller, aggS, cntS, nullptr, x1, age_emb, gen_emb);

    // layer 1 dense (tf32 mma.sync, full outputs; user self-features synthesized)
    gemm_mma<64,128,false,false,true><<<(NUx + 127) / 128, 256, SM192>>>(
        aggU, cntU, x_user_feat, Bimg + 0*32768, b1u, nullptr, u1, NUx, nullptr, x1, age_emb, gen_emb);
    gemm_mma<128,64,false,false,false><<<(NSx + 127) / 128, 256, SM192>>>(
        aggS, cntS, x_seller_feat, Bimg + 1*32768, b1s, nullptr, s1, NSx, nullptr, nullptr, nullptr, nullptr);

    // layer 2 aggregation — only mask-covered destinations are ever read
    zero_kernel<<<(NUx*32 + T - 1) / T, T>>>((float4*)aggU, (long long)NUx * 32);
    zero_kernel<<<(NSx*32 + T - 1) / T, T>>>((float4*)aggS, (long long)NSx * 32);
    scatter_warp<3,4,false,true,false><<<(int)(((long long)NEx*8 + T - 1) / T), T>>>(
        s1, src_seller, dst_user, aggU, nullptr, flagU, nullptr, nullptr, nullptr);
    scatter_warp<3,4,false,true,false><<<(int)(((long long)NEx*8 + T - 1) / T), T>>>(
        u1, src_user, dst_seller, aggS, nullptr, flagS, nullptr, nullptr, nullptr);

    // layer 2 dense, fused head-dot epilogues
    gemm_mma<128,128,true,true,false><<<(NMx + 127) / 128, 256, SM256>>>(
        aggU, cntU, u1, Bimg + 2*32768, b2u, lin_w,       partU, NMx, mask_user, nullptr, nullptr, nullptr);
    gemm_mma<128,128,true,false,false><<<(NSx + 127) / 128, 256, SM256>>>(
        aggS, cntS, s1, Bimg + 3*32768, b2s, lin_w + 128, dotS,  NSx, nullptr,   nullptr, nullptr, nullptr);

    // head
    final_kernel<<<(NMx + T - 1) / T, T>>>(mask_seller, partU, dotS, lin_b, out);
}

// round 9
// speedup vs baseline: 4.0566x; 1.0697x over previous
#include <cuda_runtime.h>
#include <math.h>
#include <stdint.h>

#define NUx 200000
#define NSx 50000
#define NEx 1000000
#define NMx 100000
#define Hx  128

// ---------------- scratch (device globals; no allocation allowed) ----------------
__device__ float g_aggU [(size_t)NUx * Hx];
__device__ float g_aggS [(size_t)NSx * Hx];
__device__ float g_aggU2[(size_t)NUx * Hx];
__device__ float g_aggS2[(size_t)NSx * Hx];
__device__ float g_u1  [(size_t)NUx * Hx];
__device__ float g_s1  [(size_t)NSx * Hx];
__device__ float g_partU[NMx];
__device__ float g_dotS [NSx];
__device__ int   g_cntU[NUx];
__device__ int   g_cntS[NSx];
__device__ unsigned char g_flagU[NUx];
__device__ unsigned char g_flagS[NSx];
__device__ uint32_t g_Bimg[4 * 32768];

__device__ __forceinline__ uint32_t f2tf32(float x) {
    uint32_t r;
    asm("cvt.rna.tf32.f32 %0, %1;" : "=r"(r) : "f"(x));
    return r;
}

// ---------------- zero fill ----------------
__global__ void zero_kernel(float4* __restrict__ p, long long n4) {
    long long i = (long long)blockIdx.x * blockDim.x + threadIdx.x;
    if (i < n4) p[i] = make_float4(0.f, 0.f, 0.f, 0.f);
}

// ---------------- set mask-membership flags ----------------
__global__ void flag_kernel(const int* __restrict__ mu, const int* __restrict__ ms,
                            unsigned char* __restrict__ fu, unsigned char* __restrict__ fs) {
    int m = blockIdx.x * blockDim.x + threadIdx.x;
    if (m >= NMx) return;
    fu[mu[m]] = 1;
    fs[ms[m]] = 1;
}

// ---------------- build tf32 weight image in m16n8k8 B-fragment layout ----------------
__global__ void build_B_kernel(const float* __restrict__ Wl, const float* __restrict__ Wr,
                               int FA, int K, uint32_t* __restrict__ img) {
    int tid = blockIdx.x * blockDim.x + threadIdx.x;
    if (tid >= K * 128) return;
    int k = tid >> 7, n = tid & 127;
    float v = (k < FA) ? Wl[k * 128 + n] : Wr[(k - FA) * 128 + n];
    int ntile = n >> 3;
    int lane  = ((n & 7) << 2) | (k & 3);
    int reg   = (k >> 2) & 1;
    int kstep = k >> 3;
    img[((ntile * (K >> 3) + kstep) * 32 + lane) * 2 + reg] = f2tf32(v);
}

// ---------------- edge scatter-add (LPE lanes/edge, NV float4 per lane) ----------------
template<int LPL, int NV, bool COUNT, bool FLAG, bool XU>
__global__ void __launch_bounds__(256)
scatter_warp(const float* __restrict__ feat,
             const int*   __restrict__ src,
             const int*   __restrict__ dst,
             float*       __restrict__ agg,
             int*         __restrict__ cnt,
             const unsigned char* __restrict__ flag,
             const int*   __restrict__ x1,
             const float* __restrict__ aemb,
             const float* __restrict__ gemb) {
    constexpr int LPE = 1 << LPL;
    constexpr int F4  = LPE * NV;
    long long gtid = (long long)blockIdx.x * blockDim.x + threadIdx.x;
    int e = (int)(gtid >> LPL);
    if (e >= NEx) return;
    const int lane = threadIdx.x & 31;
    const int sub  = lane & (LPE - 1);
    const int leader = lane & ~(LPE - 1);
    int s = 0, d = 0, f = 1, ax = 0, gx = 0;
    if (sub == 0) {
        s = src[e]; d = dst[e];
        if (FLAG) f = flag[d];
        if (XU) { int2 xx = ((const int2*)x1)[s]; ax = xx.x; gx = xx.y; }
    }
    s = __shfl_sync(0xffffffffu, s, leader);
    d = __shfl_sync(0xffffffffu, d, leader);
    if (FLAG) {
        f = __shfl_sync(0xffffffffu, f, leader);
        if (!f) return;
    }
    if (XU) {
        ax = __shfl_sync(0xffffffffu, ax, leader);
        gx = __shfl_sync(0xffffffffu, gx, leader);
    }
    float4 v[NV];
#pragma unroll
    for (int j = 0; j < NV; j++) {
        int c = j * LPE + sub;
        if (XU) {
            if (c < 8)       v[j] = ((const float4*)aemb)[ax * 8 + c];
            else if (c < 16) v[j] = ((const float4*)gemb)[gx * 8 + (c - 8)];
            else             v[j] = ((const float4*)feat)[(size_t)s * 16 + (c - 16)];
        } else {
            v[j] = ((const float4*)feat)[(size_t)s * F4 + c];
        }
    }
    float* o = agg + (size_t)d * (F4 * 4);
#pragma unroll
    for (int j = 0; j < NV; j++) {
        int c = j * LPE + sub;
        asm volatile("red.global.add.v4.f32 [%0], {%1,%2,%3,%4};"
                     :: "l"(o + c * 4), "f"(v[j].x), "f"(v[j].y), "f"(v[j].z), "f"(v[j].w)
                     : "memory");
    }
    if (COUNT && sub == 0) atomicAdd(&cnt[d], 1);
}

// ================= tf32 mma.sync GEMM core =========
template<int FA, int FB, bool DOT, bool GATHER, bool XUF>
__global__ void __launch_bounds__(256, 1)
gemm_mma(const float* __restrict__ agg, const int* __restrict__ cnt,
         const float* __restrict__ xr, const uint32_t* __restrict__ Bfrag,
         const float* __restrict__ bias, const float* __restrict__ lw,
         float* __restrict__ out, int Nrows, const int* __restrict__ mask,
         const int* __restrict__ x1, const float* __restrict__ aemb,
         const float* __restrict__ gemb)
{
    constexpr int K   = FA + FB;
    constexpr int KS  = K / 8;
    constexpr int LDA = K + 4;

    extern __shared__ uint32_t sA[];
    float* part = (float*)(sA + 128 * LDA);
    const int tid  = threadIdx.x;
    const int wid  = tid >> 5;
    const int lane = tid & 31;
    const int tile0 = blockIdx.x * 128;

    {
        const int row  = tid >> 1;
        const int half = tid & 1;
        int idx = tile0 + row; if (idx >= Nrows) idx = Nrows - 1;
        int grow = GATHER ? mask[idx] : idx;
        int c = cnt[grow];
        const float inv = 1.f / (float)(c > 1 ? c : 1);
        const float4* pa = (const float4*)(agg + (size_t)grow * FA);
        const float4* px = (const float4*)(xr  + (size_t)grow * FB);
        int ax = 0, gx = 0;
        if (XUF) { int2 xx = ((const int2*)x1)[grow]; ax = xx.x; gx = xx.y; }
#pragma unroll
        for (int j = 0; j < K / 8; j++) {
            int k4 = half * (K / 8) + j;
            int kf = k4 * 4;
            float4 v; float sc;
            if (kf < FA) { v = pa[k4]; sc = inv; }
            else if (XUF) {
                int cc = k4 - FA / 4;
                if (cc < 8)       v = ((const float4*)aemb)[ax * 8 + cc];
                else if (cc < 16) v = ((const float4*)gemb)[gx * 8 + (cc - 8)];
                else              v = ((const float4*)xr)[(size_t)grow * 16 + (cc - 16)];
                sc = 1.f;
            } else { v = px[k4 - FA / 4]; sc = 1.f; }
            uint4 t;
            t.x = f2tf32(v.x * sc); t.y = f2tf32(v.y * sc);
            t.z = f2tf32(v.z * sc); t.w = f2tf32(v.w * sc);
            *(uint4*)(sA + row * LDA + kf) = t;
        }
        if (DOT && tid < 128) part[tid] = 0.f;
    }
    __syncthreads();

    const int wm = wid & 3;
    const int wn = wid >> 2;
    const int lr = lane >> 2;
    const int lc = lane & 3;

    float acc[2][8][4];
#pragma unroll
    for (int t = 0; t < 2; t++)
#pragma unroll
        for (int nt = 0; nt < 8; nt++)
#pragma unroll
            for (int q = 0; q < 4; q++) acc[t][nt][q] = 0.f;

    const uint32_t* Ab = sA + (wm * 32 + lr) * LDA + lc;
    const uint2* Bp = (const uint2*)Bfrag + (size_t)(wn * 8) * KS * 32 + lane;

    uint2 bc[8], bn[8];
#pragma unroll
    for (int nt = 0; nt < 8; nt++) bc[nt] = Bp[nt * KS * 32];

#pragma unroll
    for (int ks = 0; ks < KS; ks++) {
        if (ks + 1 < KS) {
#pragma unroll
            for (int nt = 0; nt < 8; nt++) bn[nt] = Bp[nt * KS * 32 + (ks + 1) * 32];
        }
        uint32_t a[2][4];
#pragma unroll
        for (int t = 0; t < 2; t++) {
            const uint32_t* p = Ab + t * 16 * LDA + ks * 8;
            a[t][0] = p[0];
            a[t][1] = p[8 * LDA];
            a[t][2] = p[4];
            a[t][3] = p[8 * LDA + 4];
        }
#pragma unroll
        for (int t = 0; t < 2; t++)
#pragma unroll
            for (int nt = 0; nt < 8; nt++) {
                asm volatile(
                    "mma.sync.aligned.m16n8k8.row.col.f32.tf32.tf32.f32 "
                    "{%0,%1,%2,%3}, {%4,%5,%6,%7}, {%8,%9}, {%0,%1,%2,%3};"
                    : "+f"(acc[t][nt][0]), "+f"(acc[t][nt][1]),
                      "+f"(acc[t][nt][2]), "+f"(acc[t][nt][3])
                    : "r"(a[t][0]), "r"(a[t][1]), "r"(a[t][2]), "r"(a[t][3]),
                      "r"(bc[nt].x), "r"(bc[nt].y));
            }
#pragma unroll
        for (int nt = 0; nt < 8; nt++) bc[nt] = bn[nt];
    }

    if (!DOT) {
#pragma unroll
        for (int nt = 0; nt < 8; nt++) {
            const int col = wn * 64 + nt * 8 + lc * 2;
            const float2 bv = *(const float2*)(bias + col);
#pragma unroll
            for (int t = 0; t < 2; t++) {
                int r0 = tile0 + wm * 32 + t * 16 + lr;
                if (r0 < Nrows) {
                    float2 o;
                    o.x = fmaxf(acc[t][nt][0] + bv.x, 0.f);
                    o.y = fmaxf(acc[t][nt][1] + bv.y, 0.f);
                    *(float2*)(out + (size_t)r0 * 128 + col) = o;
                }
                int r1 = r0 + 8;
                if (r1 < Nrows) {
                    float2 o;
                    o.x = fmaxf(acc[t][nt][2] + bv.x, 0.f);
                    o.y = fmaxf(acc[t][nt][3] + bv.y, 0.f);
                    *(float2*)(out + (size_t)r1 * 128 + col) = o;
                }
            }
        }
    } else {
        float p[2][2] = {{0.f, 0.f}, {0.f, 0.f}};
#pragma unroll
        for (int nt = 0; nt < 8; nt++) {
            const int col = wn * 64 + nt * 8 + lc * 2;
            const float2 bv = *(const float2*)(bias + col);
            const float2 wv = *(const float2*)(lw + col);
#pragma unroll
            for (int t = 0; t < 2; t++) {
                p[t][0] += fmaxf(acc[t][nt][0] + bv.x, 0.f) * wv.x
                         + fmaxf(acc[t][nt][1] + bv.y, 0.f) * wv.y;
                p[t][1] += fmaxf(acc[t][nt][2] + bv.x, 0.f) * wv.x
                         + fmaxf(acc[t][nt][3] + bv.y, 0.f) * wv.y;
            }
        }
#pragma unroll
        for (int t = 0; t < 2; t++)
#pragma unroll
            for (int h = 0; h < 2; h++) {
                p[t][h] += __shfl_xor_sync(0xffffffffu, p[t][h], 1);
                p[t][h] += __shfl_xor_sync(0xffffffffu, p[t][h], 2);
            }
        if (lc == 0) {
#pragma unroll
            for (int t = 0; t < 2; t++) {
                atomicAdd(&part[wm * 32 + t * 16 + lr],     p[t][0]);
                atomicAdd(&part[wm * 32 + t * 16 + lr + 8], p[t][1]);
            }
        }
        __syncthreads();
        if (tid < 128) {
            int idx = tile0 + tid;
            if (idx < Nrows) out[idx] = part[tid];
        }
    }
}

// ---------------- head: partials -> sigmoid ----------------
__global__ void final_kernel(const int* __restrict__ ms,
                             const float* __restrict__ partU,
                             const float* __restrict__ dotS,
                             const float* __restrict__ lb,
                             float* __restrict__ out) {
    int m = blockIdx.x * blockDim.x + threadIdx.x;
    if (m >= NMx) return;
    float s = partU[m] + dotS[ms[m]] + lb[0];
    out[m] = 1.f / (1.f + expf(-s));
}

// ---------------- launcher (dual-stream; every record precedes its wait) ----------------
extern "C" void kernel_launch(void* const* d_in, const int* in_sizes, int n_in,
                              void* d_out, int out_size) {
    (void)in_sizes; (void)n_in; (void)out_size;
    const float* x_user_feat   = (const float*)d_in[0];
    const float* x_seller_feat = (const float*)d_in[1];
    const int*   x1            = (const int*)  d_in[2];
    const int*   src_user      = (const int*)  d_in[3];
    const int*   dst_seller    = (const int*)  d_in[4];
    const int*   src_seller    = (const int*)  d_in[5];
    const int*   dst_user      = (const int*)  d_in[6];
    const int*   mask_user     = (const int*)  d_in[7];
    const int*   mask_seller   = (const int*)  d_in[8];
    const float* age_emb       = (const float*)d_in[9];
    const float* gen_emb       = (const float*)d_in[10];
    const float* W1ul = (const float*)d_in[11];
    const float* W1ur = (const float*)d_in[12];
    const float* b1u  = (const float*)d_in[13];
    const float* W1sl = (const float*)d_in[14];
    const float* W1sr = (const float*)d_in[15];
    const float* b1s  = (const float*)d_in[16];
    const float* W2ul = (const float*)d_in[17];
    const float* W2ur = (const float*)d_in[18];
    const float* b2u  = (const float*)d_in[19];
    const float* W2sl = (const float*)d_in[20];
    const float* W2sr = (const float*)d_in[21];
    const float* b2s  = (const float*)d_in[22];
    const float* lin_w = (const float*)d_in[23];
    const float* lin_b = (const float*)d_in[24];
    float* out = (float*)d_out;

    float *aggU, *aggS, *aggU2, *aggS2, *u1, *s1, *partU, *dotS;
    int *cntU, *cntS;
    unsigned char *flagU, *flagS;
    uint32_t* Bimg;
    cudaGetSymbolAddress((void**)&aggU,  g_aggU);
    cudaGetSymbolAddress((void**)&aggS,  g_aggS);
    cudaGetSymbolAddress((void**)&aggU2, g_aggU2);
    cudaGetSymbolAddress((void**)&aggS2, g_aggS2);
    cudaGetSymbolAddress((void**)&u1,    g_u1);
    cudaGetSymbolAddress((void**)&s1,    g_s1);
    cudaGetSymbolAddress((void**)&partU, g_partU);
    cudaGetSymbolAddress((void**)&dotS,  g_dotS);
    cudaGetSymbolAddress((void**)&cntU,  g_cntU);
    cudaGetSymbolAddress((void**)&cntS,  g_cntS);
    cudaGetSymbolAddress((void**)&flagU, g_flagU);
    cudaGetSymbolAddress((void**)&flagS, g_flagS);
    cudaGetSymbolAddress((void**)&Bimg,  g_Bimg);

    const int SM192 = 128 * (192 + 4) * 4;
    const int SM256 = 128 * (256 + 4) * 4 + 512;
    cudaFuncSetAttribute((const void*)gemm_mma<64,128,false,false,true>,
                         cudaFuncAttributeMaxDynamicSharedMemorySize, SM192);
    cudaFuncSetAttribute((const void*)gemm_mma<128,64,false,false,false>,
                         cudaFuncAttributeMaxDynamicSharedMemorySize, SM192);
    cudaFuncSetAttribute((const void*)gemm_mma<128,128,true,true,false>,
                         cudaFuncAttributeMaxDynamicSharedMemorySize, SM256);
    cudaFuncSetAttribute((const void*)gemm_mma<128,128,true,false,false>,
                         cudaFuncAttributeMaxDynamicSharedMemorySize, SM256);

    static cudaStream_t s2 = nullptr;
    static cudaEvent_t evF, evFlag, evU1, evS1, evG2U;
    if (!s2) {
        cudaStreamCreateWithFlags(&s2, cudaStreamNonBlocking);
        cudaEventCreateWithFlags(&evF,    cudaEventDisableTiming);
        cudaEventCreateWithFlags(&evFlag, cudaEventDisableTiming);
        cudaEventCreateWithFlags(&evU1,   cudaEventDisableTiming);
        cudaEventCreateWithFlags(&evS1,   cudaEventDisableTiming);
        cudaEventCreateWithFlags(&evG2U,  cudaEventDisableTiming);
    }
    cudaStream_t s0 = 0;

    const int T = 256;

    // ---- fork ----
    cudaEventRecord(evF, s0);
    cudaStreamWaitEvent(s2, evF, 0);

    // ---- s0: prep (zeros, B images, flags) ----
    zero_kernel<<<(NUx*32 + T - 1) / T, T, 0, s0>>>((float4*)aggU, (long long)NUx * 32);
    zero_kernel<<<(NSx*32 + T - 1) / T, T, 0, s0>>>((float4*)aggS2, (long long)NSx * 32);
    zero_kernel<<<(NUx/4  + T - 1) / T, T, 0, s0>>>((float4*)cntU, NUx / 4);
    zero_kernel<<<(NUx/16 + T - 1) / T, T, 0, s0>>>((float4*)flagU, NUx / 16);
    zero_kernel<<<(NSx/16 + T - 1) / T, T, 0, s0>>>((float4*)flagS, NSx / 16);
    build_B_kernel<<<(192*128 + T - 1) / T, T, 0, s0>>>(W1ul, W1ur,  64, 192, Bimg + 0*32768);
    build_B_kernel<<<(256*128 + T - 1) / T, T, 0, s0>>>(W2ul, W2ur, 128, 256, Bimg + 2*32768);
    build_B_kernel<<<(256*128 + T - 1) / T, T, 0, s0>>>(W2sl, W2sr, 128, 256, Bimg + 3*32768);
    flag_kernel<<<(NMx + T - 1) / T, T, 0, s0>>>(mask_user, mask_seller, flagU, flagS);
    cudaEventRecord(evFlag, s0);

    // ---- s2: seller layer-1 chain (record evS1 BEFORE s0 waits on it) ----
    zero_kernel<<<(NSx*32 + T - 1) / T, T, 0, s2>>>((float4*)aggS, (long long)NSx * 32);
    zero_kernel<<<(NUx*32 + T - 1) / T, T, 0, s2>>>((float4*)aggU2, (long long)NUx * 32);
    zero_kernel<<<(NSx/4  + T - 1) / T, T, 0, s2>>>((float4*)cntS, NSx / 4);
    build_B_kernel<<<(192*128 + T - 1) / T, T, 0, s2>>>(W1sl, W1sr, 128, 192, Bimg + 1*32768);
    scatter_warp<3,4,true,false,true><<<(int)(((long long)NEx*8 + T - 1) / T), T, 0, s2>>>(
        x_user_feat, src_user, dst_seller, aggS, cntS, nullptr, x1, age_emb, gen_emb);
    gemm_mma<128,64,false,false,false><<<(NSx + 127) / 128, 256, SM192, s2>>>(
        aggS, cntS, x_seller_feat, Bimg + 1*32768, b1s, nullptr, s1, NSx, nullptr, nullptr, nullptr, nullptr);
    cudaEventRecord(evS1, s2);

    // ---- s0: user layer-1 chain ----
    scatter_warp<2,4,true,false,false><<<(int)(((long long)NEx*4 + T - 1) / T), T, 0, s0>>>(
        x_seller_feat, src_seller, dst_user, aggU, cntU, nullptr, nullptr, nullptr, nullptr);
    gemm_mma<64,128,false,false,true><<<(NUx + 127) / 128, 256, SM192, s0>>>(
        aggU, cntU, x_user_feat, Bimg + 0*32768, b1u, nullptr, u1, NUx, nullptr, x1, age_emb, gen_emb);
    cudaEventRecord(evU1, s0);

    // ---- s0: layer-2 seller branch (u1 -> aggS2, then gemm2s after evS1) ----
    scatter_warp<3,4,false,true,false><<<(int)(((long long)NEx*8 + T - 1) / T), T, 0, s0>>>(
        u1, src_user, dst_seller, aggS2, nullptr, flagS, nullptr, nullptr, nullptr);
    cudaStreamWaitEvent(s0, evS1, 0);
    gemm_mma<128,128,true,false,false><<<(NSx + 127) / 128, 256, SM256, s0>>>(
        aggS2, cntS, s1, Bimg + 3*32768, b2s, lin_w + 128, dotS, NSx, nullptr, nullptr, nullptr, nullptr);

    // ---- s2: layer-2 user branch (s1 -> aggU2 after evFlag, gemm2u after evU1) ----
    cudaStreamWaitEvent(s2, evFlag, 0);
    scatter_warp<3,4,false,true,false><<<(int)(((long long)NEx*8 + T - 1) / T), T, 0, s2>>>(
        s1, src_seller, dst_user, aggU2, nullptr, flagU, nullptr, nullptr, nullptr);
    cudaStreamWaitEvent(s2, evU1, 0);
    gemm_mma<128,128,true,true,false><<<(NMx + 127) / 128, 256, SM256, s2>>>(
        aggU2, cntU, u1, Bimg + 2*32768, b2u, lin_w, partU, NMx, mask_user, nullptr, nullptr, nullptr);
    cudaEventRecord(evG2U, s2);

    // ---- join + head ----
    cudaStreamWaitEvent(s0, evG2U, 0);
    final_kernel<<<(NMx + T - 1) / T, T, 0, s0>>>(mask_seller, partU, dotS, lin_b, out);
}

// round 10
// speedup vs baseline: 4.7444x; 1.1695x over previous
#include <cuda_runtime.h>
#include <math.h>
#include <stdint.h>

#define NUx 200000
#define NSx 50000
#define NEx 1000000
#define NMx 100000
#define Hx  128

// ---------------- scratch (device globals; no allocation allowed) ----------------
__device__ float g_aggU [(size_t)NUx * Hx];
__device__ float g_aggS [(size_t)NSx * Hx];
__device__ float g_aggU2[(size_t)NUx * Hx];
__device__ float g_aggS2[(size_t)NSx * Hx];
__device__ float g_u1  [(size_t)NUx * Hx];
__device__ float g_s1  [(size_t)NSx * Hx];
__device__ float g_partU[NMx];
__device__ float g_dotS [NSx];
__device__ int   g_cntU[NUx];
__device__ int   g_cntS[NSx];
__device__ int   g_offU[NUx];
__device__ int   g_offS[NSx];
__device__ int   g_curU[NUx];
__device__ int   g_curS[NSx];
__device__ int   g_csrU[NEx];           // neighbors (sellers) of each user
__device__ int   g_csrS[NEx];           // neighbors (users) of each seller
__device__ int   g_alloc[2];
__device__ unsigned char g_flagU[NUx];
__device__ unsigned char g_flagS[NSx];
__device__ uint32_t g_Bimg[4 * 32768];

__device__ __forceinline__ uint32_t f2tf32(float x) {
    uint32_t r;
    asm("cvt.rna.tf32.f32 %0, %1;" : "=r"(r) : "f"(x));
    return r;
}

// ---------------- prep: zero counts/cursors/flags/alloc ----------------
__global__ void prep_zero(int* cntU, int* cntS, unsigned char* fu, unsigned char* fs, int* alloc2) {
    int i = blockIdx.x * blockDim.x + threadIdx.x;
    if (i < NUx) { cntU[i] = 0; fu[i] = 0; }
    if (i < NSx) { cntS[i] = 0; fs[i] = 0; }
    if (i < 2)   alloc2[i] = 0;
}

// ---------------- set mask-membership flags ----------------
__global__ void flag_kernel(const int* __restrict__ mu, const int* __restrict__ ms,
                            unsigned char* __restrict__ fu, unsigned char* __restrict__ fs) {
    int m = blockIdx.x * blockDim.x + threadIdx.x;
    if (m >= NMx) return;
    fu[mu[m]] = 1;
    fs[ms[m]] = 1;
}

// ---------------- degree counts ----------------
__global__ void count_kernel(const int* __restrict__ dst_user, const int* __restrict__ dst_seller,
                             int* __restrict__ cntU, int* __restrict__ cntS) {
    int e = blockIdx.x * blockDim.x + threadIdx.x;
    if (e >= NEx) return;
    atomicAdd(&cntU[dst_user[e]], 1);
    atomicAdd(&cntS[dst_seller[e]], 1);
}

// ---------------- CSR segment allocation (block scan + atomic bump) ----------------
__global__ void __launch_bounds__(256)
alloc_kernel(const int* __restrict__ cnt, int* __restrict__ off, int* __restrict__ cur,
             int N, int* __restrict__ alloc2, int cidx) {
    __shared__ int sc[256];
    __shared__ int base;
    int i = blockIdx.x * 256 + threadIdx.x;
    int v = (i < N) ? cnt[i] : 0;
    sc[threadIdx.x] = v;
    __syncthreads();
#pragma unroll
    for (int d = 1; d < 256; d <<= 1) {
        int t = (threadIdx.x >= d) ? sc[threadIdx.x - d] : 0;
        __syncthreads();
        sc[threadIdx.x] += t;
        __syncthreads();
    }
    if (threadIdx.x == 255) base = atomicAdd(&alloc2[cidx], sc[255]);
    __syncthreads();
    if (i < N) {
        int excl = sc[threadIdx.x] - v + base;
        off[i] = excl;
        cur[i] = excl;
    }
}

// ---------------- CSR fill ----------------
__global__ void fill_kernel(const int* __restrict__ src_user, const int* __restrict__ dst_seller,
                            const int* __restrict__ src_seller, const int* __restrict__ dst_user,
                            int* __restrict__ curU, int* __restrict__ curS,
                            int* __restrict__ csrU, int* __restrict__ csrS) {
    int e = blockIdx.x * blockDim.x + threadIdx.x;
    if (e >= NEx) return;
    int du = dst_user[e];
    int p = atomicAdd(&curU[du], 1);
    csrU[p] = src_seller[e];
    int ds = dst_seller[e];
    int q = atomicAdd(&curS[ds], 1);
    csrS[q] = src_user[e];
}

// ---------------- CSR gather: sum neighbor rows, write each agg row once ----------------
// F4 = 1<<LG float4s per row; one lane owns one float4 column. FLAG: skip unread rows.
// XU: neighbor row synthesized as [age_emb|gen_emb|feat].
template<int LG, bool FLAG, bool XU>
__global__ void __launch_bounds__(256)
gather_rows(const float* __restrict__ feat, const int* __restrict__ csr,
            const int* __restrict__ off, const int* __restrict__ cnt,
            float* __restrict__ agg, int Nrows, const unsigned char* __restrict__ flag,
            const int* __restrict__ x1, const float* __restrict__ aemb,
            const float* __restrict__ gemb)
{
    constexpr int F4 = 1 << LG;
    long long g = (long long)blockIdx.x * blockDim.x + threadIdx.x;
    int r = (int)(g >> LG);
    if (r >= Nrows) return;
    if (FLAG && !flag[r]) return;
    const int c = threadIdx.x & (F4 - 1);
    const int o = off[r], n = cnt[r];

    auto ld = [&](int nb) -> float4 {
        if (XU) {
            if (c < 8)  return ((const float4*)aemb)[((const int2*)x1)[nb].x * 8 + c];
            if (c < 16) return ((const float4*)gemb)[((const int2*)x1)[nb].y * 8 + (c - 8)];
            return ((const float4*)feat)[(size_t)nb * 16 + (c - 16)];
        }
        return ((const float4*)feat)[(size_t)nb * F4 + c];
    };

    float4 acc = make_float4(0.f, 0.f, 0.f, 0.f);
    int i = 0;
    for (; i + 2 <= n; i += 2) {
        int nb0 = csr[o + i], nb1 = csr[o + i + 1];
        float4 a = ld(nb0);
        float4 b = ld(nb1);
        acc.x += a.x + b.x; acc.y += a.y + b.y;
        acc.z += a.z + b.z; acc.w += a.w + b.w;
    }
    if (i < n) {
        float4 a = ld(csr[o + i]);
        acc.x += a.x; acc.y += a.y; acc.z += a.z; acc.w += a.w;
    }
    ((float4*)agg)[(size_t)r * F4 + c] = acc;
}

// ---------------- build tf32 weight image in m16n8k8 B-fragment layout ----------------
__global__ void build_B_kernel(const float* __restrict__ Wl, const float* __restrict__ Wr,
                               int FA, int K, uint32_t* __restrict__ img) {
    int tid = blockIdx.x * blockDim.x + threadIdx.x;
    if (tid >= K * 128) return;
    int k = tid >> 7, n = tid & 127;
    float v = (k < FA) ? Wl[k * 128 + n] : Wr[(k - FA) * 128 + n];
    int ntile = n >> 3;
    int lane  = ((n & 7) << 2) | (k & 3);
    int reg   = (k >> 2) & 1;
    int kstep = k >> 3;
    img[((ntile * (K >> 3) + kstep) * 32 + lane) * 2 + reg] = f2tf32(v);
}

// ================= tf32 mma.sync GEMM core =========
template<int FA, int FB, bool DOT, bool GATHER, bool XUF>
__global__ void __launch_bounds__(256, 1)
gemm_mma(const float* __restrict__ agg, const int* __restrict__ cnt,
         const float* __restrict__ xr, const uint32_t* __restrict__ Bfrag,
         const float* __restrict__ bias, const float* __restrict__ lw,
         float* __restrict__ out, int Nrows, const int* __restrict__ mask,
         const int* __restrict__ x1, const float* __restrict__ aemb,
         const float* __restrict__ gemb)
{
    constexpr int K   = FA + FB;
    constexpr int KS  = K / 8;
    constexpr int LDA = K + 4;

    extern __shared__ uint32_t sA[];
    float* part = (float*)(sA + 128 * LDA);
    const int tid  = threadIdx.x;
    const int wid  = tid >> 5;
    const int lane = tid & 31;
    const int tile0 = blockIdx.x * 128;

    {
        const int row  = tid >> 1;
        const int half = tid & 1;
        int idx = tile0 + row; if (idx >= Nrows) idx = Nrows - 1;
        int grow = GATHER ? mask[idx] : idx;
        int c = cnt[grow];
        const float inv = 1.f / (float)(c > 1 ? c : 1);
        const float4* pa = (const float4*)(agg + (size_t)grow * FA);
        const float4* px = (const float4*)(xr  + (size_t)grow * FB);
        int ax = 0, gx = 0;
        if (XUF) { int2 xx = ((const int2*)x1)[grow]; ax = xx.x; gx = xx.y; }
#pragma unroll
        for (int j = 0; j < K / 8; j++) {
            int k4 = half * (K / 8) + j;
            int kf = k4 * 4;
            float4 v; float sc;
            if (kf < FA) { v = pa[k4]; sc = inv; }
            else if (XUF) {
                int cc = k4 - FA / 4;
                if (cc < 8)       v = ((const float4*)aemb)[ax * 8 + cc];
                else if (cc < 16) v = ((const float4*)gemb)[gx * 8 + (cc - 8)];
                else              v = ((const float4*)xr)[(size_t)grow * 16 + (cc - 16)];
                sc = 1.f;
            } else { v = px[k4 - FA / 4]; sc = 1.f; }
            uint4 t;
            t.x = f2tf32(v.x * sc); t.y = f2tf32(v.y * sc);
            t.z = f2tf32(v.z * sc); t.w = f2tf32(v.w * sc);
            *(uint4*)(sA + row * LDA + kf) = t;
        }
        if (DOT && tid < 128) part[tid] = 0.f;
    }
    __syncthreads();

    const int wm = wid & 3;
    const int wn = wid >> 2;
    const int lr = lane >> 2;
    const int lc = lane & 3;

    float acc[2][8][4];
#pragma unroll
    for (int t = 0; t < 2; t++)
#pragma unroll
        for (int nt = 0; nt < 8; nt++)
#pragma unroll
            for (int q = 0; q < 4; q++) acc[t][nt][q] = 0.f;

    const uint32_t* Ab = sA + (wm * 32 + lr) * LDA + lc;
    const uint2* Bp = (const uint2*)Bfrag + (size_t)(wn * 8) * KS * 32 + lane;

    uint2 bc[8], bn[8];
#pragma unroll
    for (int nt = 0; nt < 8; nt++) bc[nt] = Bp[nt * KS * 32];

#pragma unroll
    for (int ks = 0; ks < KS; ks++) {
        if (ks + 1 < KS) {
#pragma unroll
            for (int nt = 0; nt < 8; nt++) bn[nt] = Bp[nt * KS * 32 + (ks + 1) * 32];
        }
        uint32_t a[2][4];
#pragma unroll
        for (int t = 0; t < 2; t++) {
            const uint32_t* p = Ab + t * 16 * LDA + ks * 8;
            a[t][0] = p[0];
            a[t][1] = p[8 * LDA];
            a[t][2] = p[4];
            a[t][3] = p[8 * LDA + 4];
        }
#pragma unroll
        for (int t = 0; t < 2; t++)
#pragma unroll
            for (int nt = 0; nt < 8; nt++) {
                asm volatile(
                    "mma.sync.aligned.m16n8k8.row.col.f32.tf32.tf32.f32 "
                    "{%0,%1,%2,%3}, {%4,%5,%6,%7}, {%8,%9}, {%0,%1,%2,%3};"
                    : "+f"(acc[t][nt][0]), "+f"(acc[t][nt][1]),
                      "+f"(acc[t][nt][2]), "+f"(acc[t][nt][3])
                    : "r"(a[t][0]), "r"(a[t][1]), "r"(a[t][2]), "r"(a[t][3]),
                      "r"(bc[nt].x), "r"(bc[nt].y));
            }
#pragma unroll
        for (int nt = 0; nt < 8; nt++) bc[nt] = bn[nt];
    }

    if (!DOT) {
#pragma unroll
        for (int nt = 0; nt < 8; nt++) {
            const int col = wn * 64 + nt * 8 + lc * 2;
            const float2 bv = *(const float2*)(bias + col);
#pragma unroll
            for (int t = 0; t < 2; t++) {
                int r0 = tile0 + wm * 32 + t * 16 + lr;
                if (r0 < Nrows) {
                    float2 o;
                    o.x = fmaxf(acc[t][nt][0] + bv.x, 0.f);
                    o.y = fmaxf(acc[t][nt][1] + bv.y, 0.f);
                    *(float2*)(out + (size_t)r0 * 128 + col) = o;
                }
                int r1 = r0 + 8;
                if (r1 < Nrows) {
                    float2 o;
                    o.x = fmaxf(acc[t][nt][2] + bv.x, 0.f);
                    o.y = fmaxf(acc[t][nt][3] + bv.y, 0.f);
                    *(float2*)(out + (size_t)r1 * 128 + col) = o;
                }
            }
        }
    } else {
        float p[2][2] = {{0.f, 0.f}, {0.f, 0.f}};
#pragma unroll
        for (int nt = 0; nt < 8; nt++) {
            const int col = wn * 64 + nt * 8 + lc * 2;
            const float2 bv = *(const float2*)(bias + col);
            const float2 wv = *(const float2*)(lw + col);
#pragma unroll
            for (int t = 0; t < 2; t++) {
                p[t][0] += fmaxf(acc[t][nt][0] + bv.x, 0.f) * wv.x
                         + fmaxf(acc[t][nt][1] + bv.y, 0.f) * wv.y;
                p[t][1] += fmaxf(acc[t][nt][2] + bv.x, 0.f) * wv.x
                         + fmaxf(acc[t][nt][3] + bv.y, 0.f) * wv.y;
            }
        }
#pragma unroll
        for (int t = 0; t < 2; t++)
#pragma unroll
            for (int h = 0; h < 2; h++) {
                p[t][h] += __shfl_xor_sync(0xffffffffu, p[t][h], 1);
                p[t][h] += __shfl_xor_sync(0xffffffffu, p[t][h], 2);
            }
        if (lc == 0) {
#pragma unroll
            for (int t = 0; t < 2; t++) {
                atomicAdd(&part[wm * 32 + t * 16 + lr],     p[t][0]);
                atomicAdd(&part[wm * 32 + t * 16 + lr + 8], p[t][1]);
            }
        }
        __syncthreads();
        if (tid < 128) {
            int idx = tile0 + tid;
            if (idx < Nrows) out[idx] = part[tid];
        }
    }
}

// ---------------- head ----------------
__global__ void final_kernel(const int* __restrict__ ms,
                             const float* __restrict__ partU,
                             const float* __restrict__ dotS,
                             const float* __restrict__ lb,
                             float* __restrict__ out) {
    int m = blockIdx.x * blockDim.x + threadIdx.x;
    if (m >= NMx) return;
    float s = partU[m] + dotS[ms[m]] + lb[0];
    out[m] = 1.f / (1.f + expf(-s));
}

// ---------------- launcher ----------------
extern "C" void kernel_launch(void* const* d_in, const int* in_sizes, int n_in,
                              void* d_out, int out_size) {
    (void)in_sizes; (void)n_in; (void)out_size;
    const float* x_user_feat   = (const float*)d_in[0];
    const float* x_seller_feat = (const float*)d_in[1];
    const int*   x1            = (const int*)  d_in[2];
    const int*   src_user      = (const int*)  d_in[3];
    const int*   dst_seller    = (const int*)  d_in[4];
    const int*   src_seller    = (const int*)  d_in[5];
    const int*   dst_user      = (const int*)  d_in[6];
    const int*   mask_user     = (const int*)  d_in[7];
    const int*   mask_seller   = (const int*)  d_in[8];
    const float* age_emb       = (const float*)d_in[9];
    const float* gen_emb       = (const float*)d_in[10];
    const float* W1ul = (const float*)d_in[11];
    const float* W1ur = (const float*)d_in[12];
    const float* b1u  = (const float*)d_in[13];
    const float* W1sl = (const float*)d_in[14];
    const float* W1sr = (const float*)d_in[15];
    const float* b1s  = (const float*)d_in[16];
    const float* W2ul = (const float*)d_in[17];
    const float* W2ur = (const float*)d_in[18];
    const float* b2u  = (const float*)d_in[19];
    const float* W2sl = (const float*)d_in[20];
    const float* W2sr = (const float*)d_in[21];
    const float* b2s  = (const float*)d_in[22];
    const float* lin_w = (const float*)d_in[23];
    const float* lin_b = (const float*)d_in[24];
    float* out = (float*)d_out;

    float *aggU, *aggS, *aggU2, *aggS2, *u1, *s1, *partU, *dotS;
    int *cntU, *cntS, *offU, *offS, *curU, *curS, *csrU, *csrS, *alloc2;
    unsigned char *flagU, *flagS;
    uint32_t* Bimg;
    cudaGetSymbolAddress((void**)&aggU,  g_aggU);
    cudaGetSymbolAddress((void**)&aggS,  g_aggS);
    cudaGetSymbolAddress((void**)&aggU2, g_aggU2);
    cudaGetSymbolAddress((void**)&aggS2, g_aggS2);
    cudaGetSymbolAddress((void**)&u1,    g_u1);
    cudaGetSymbolAddress((void**)&s1,    g_s1);
    cudaGetSymbolAddress((void**)&partU, g_partU);
    cudaGetSymbolAddress((void**)&dotS,  g_dotS);
    cudaGetSymbolAddress((void**)&cntU,  g_cntU);
    cudaGetSymbolAddress((void**)&cntS,  g_cntS);
    cudaGetSymbolAddress((void**)&offU,  g_offU);
    cudaGetSymbolAddress((void**)&offS,  g_offS);
    cudaGetSymbolAddress((void**)&curU,  g_curU);
    cudaGetSymbolAddress((void**)&curS,  g_curS);
    cudaGetSymbolAddress((void**)&csrU,  g_csrU);
    cudaGetSymbolAddress((void**)&csrS,  g_csrS);
    cudaGetSymbolAddress((void**)&alloc2, g_alloc);
    cudaGetSymbolAddress((void**)&flagU, g_flagU);
    cudaGetSymbolAddress((void**)&flagS, g_flagS);
    cudaGetSymbolAddress((void**)&Bimg,  g_Bimg);

    const int SM192 = 128 * (192 + 4) * 4;
    const int SM256 = 128 * (256 + 4) * 4 + 512;
    cudaFuncSetAttribute((const void*)gemm_mma<64,128,false,false,true>,
                         cudaFuncAttributeMaxDynamicSharedMemorySize, SM192);
    cudaFuncSetAttribute((const void*)gemm_mma<128,64,false,false,false>,
                         cudaFuncAttributeMaxDynamicSharedMemorySize, SM192);
    cudaFuncSetAttribute((const void*)gemm_mma<128,128,true,true,false>,
                         cudaFuncAttributeMaxDynamicSharedMemorySize, SM256);
    cudaFuncSetAttribute((const void*)gemm_mma<128,128,true,false,false>,
                         cudaFuncAttributeMaxDynamicSharedMemorySize, SM256);

    static cudaStream_t s2 = nullptr;
    static cudaEvent_t evF, evCSR, evU1, evS1, evG2U;
    if (!s2) {
        cudaStreamCreateWithFlags(&s2, cudaStreamNonBlocking);
        cudaEventCreateWithFlags(&evF,   cudaEventDisableTiming);
        cudaEventCreateWithFlags(&evCSR, cudaEventDisableTiming);
        cudaEventCreateWithFlags(&evU1,  cudaEventDisableTiming);
        cudaEventCreateWithFlags(&evS1,  cudaEventDisableTiming);
        cudaEventCreateWithFlags(&evG2U, cudaEventDisableTiming);
    }
    cudaStream_t s0 = 0;
    const int T = 256;

    // ---- fork ----
    cudaEventRecord(evF, s0);
    cudaStreamWaitEvent(s2, evF, 0);

    // ---- s0: CSR build + flags ----
    prep_zero<<<(NUx + T - 1) / T, T, 0, s0>>>(cntU, cntS, flagU, flagS, alloc2);
    flag_kernel<<<(NMx + T - 1) / T, T, 0, s0>>>(mask_user, mask_seller, flagU, flagS);
    count_kernel<<<(NEx + T - 1) / T, T, 0, s0>>>(dst_user, dst_seller, cntU, cntS);
    alloc_kernel<<<(NUx + 255) / 256, 256, 0, s0>>>(cntU, offU, curU, NUx, alloc2, 0);
    alloc_kernel<<<(NSx + 255) / 256, 256, 0, s0>>>(cntS, offS, curS, NSx, alloc2, 1);
    fill_kernel<<<(NEx + T - 1) / T, T, 0, s0>>>(src_user, dst_seller, src_seller, dst_user,
                                                 curU, curS, csrU, csrS);
    cudaEventRecord(evCSR, s0);

    // ---- s2: B images (independent) then seller layer-1 chain ----
    build_B_kernel<<<(192*128 + T - 1) / T, T, 0, s2>>>(W1sl, W1sr, 128, 192, Bimg + 1*32768);
    build_B_kernel<<<(256*128 + T - 1) / T, T, 0, s2>>>(W2ul, W2ur, 128, 256, Bimg + 2*32768);
    build_B_kernel<<<(256*128 + T - 1) / T, T, 0, s2>>>(W2sl, W2sr, 128, 256, Bimg + 3*32768);
    cudaStreamWaitEvent(s2, evCSR, 0);
    gather_rows<5,false,true><<<(NSx * 32 + T - 1) / T, T, 0, s2>>>(
        x_user_feat, csrS, offS, cntS, aggS, NSx, nullptr, x1, age_emb, gen_emb);
    gemm_mma<128,64,false,false,false><<<(NSx + 127) / 128, 256, SM192, s2>>>(
        aggS, cntS, x_seller_feat, Bimg + 1*32768, b1s, nullptr, s1, NSx, nullptr, nullptr, nullptr, nullptr);
    cudaEventRecord(evS1, s2);

    // ---- s0: user layer-1 chain + layer-2 seller branch ----
    build_B_kernel<<<(192*128 + T - 1) / T, T, 0, s0>>>(W1ul, W1ur, 64, 192, Bimg + 0*32768);
    gather_rows<4,false,false><<<(NUx * 16 + T - 1) / T, T, 0, s0>>>(
        x_seller_feat, csrU, offU, cntU, aggU, NUx, nullptr, nullptr, nullptr, nullptr);
    gemm_mma<64,128,false,false,true><<<(NUx + 127) / 128, 256, SM192, s0>>>(
        aggU, cntU, x_user_feat, Bimg + 0*32768, b1u, nullptr, u1, NUx, nullptr, x1, age_emb, gen_emb);
    cudaEventRecord(evU1, s0);
    gather_rows<5,true,false><<<(NSx * 32 + T - 1) / T, T, 0, s0>>>(
        u1, csrS, offS, cntS, aggS2, NSx, flagS, nullptr, nullptr, nullptr);
    cudaStreamWaitEvent(s0, evS1, 0);
    gemm_mma<128,128,true,false,false><<<(NSx + 127) / 128, 256, SM256, s0>>>(
        aggS2, cntS, s1, Bimg + 3*32768, b2s, lin_w + 128, dotS, NSx, nullptr, nullptr, nullptr, nullptr);

    // ---- s2: layer-2 user branch ----
    gather_rows<5,true,false><<<(NUx * 32 + T - 1) / T, T, 0, s2>>>(
        s1, csrU, offU, cntU, aggU2, NUx, flagU, nullptr, nullptr, nullptr);
    cudaStreamWaitEvent(s2, evU1, 0);
    gemm_mma<128,128,true,true,false><<<(NMx + 127) / 128, 256, SM256, s2>>>(
        aggU2, cntU, u1, Bimg + 2*32768, b2u, lin_w, partU, NMx, mask_user, nullptr, nullptr, nullptr);
    cudaEventRecord(evG2U, s2);

    // ---- join + head ----
    cudaStreamWaitEvent(s0, evG2U, 0);
    final_kernel<<<(NMx + T - 1) / T, T, 0, s0>>>(mask_seller, partU, dotS, lin_b, out);
}

// round 11
// speedup vs baseline: 4.9664x; 1.0468x over previous
#include <cuda_runtime.h>
#include <math.h>
#include <stdint.h>

#define NUx 200000
#define NSx 50000
#define NEx 1000000
#define NMx 100000
#define Hx  128

// ---------------- scratch (device globals; no allocation allowed) ----------------
__device__ float g_aggU [(size_t)NUx * Hx];
__device__ float g_aggS [(size_t)NSx * Hx];
__device__ float g_aggU2[(size_t)NUx * Hx];
__device__ float g_aggS2[(size_t)NSx * Hx];
__device__ float g_u1  [(size_t)NUx * Hx];
__device__ float g_s1  [(size_t)NSx * Hx];
__device__ float g_partU[NMx];
__device__ float g_dotS [NSx];
__device__ int   g_cntU[NUx];
__device__ int   g_cntS[NSx];
__device__ int   g_offU[NUx];
__device__ int   g_offS[NSx];
__device__ int   g_curU[NUx];
__device__ int   g_curS[NSx];
__device__ int   g_csrU[NEx];
__device__ int   g_csrS[NEx];
__device__ int   g_alloc[2];
__device__ unsigned char g_flagU[NUx];
__device__ unsigned char g_flagS[NSx];
__device__ uint32_t g_Bimg[4 * 32768];

__device__ __forceinline__ uint32_t f2tf32(float x) {
    uint32_t r;
    asm("cvt.rna.tf32.f32 %0, %1;" : "=r"(r) : "f"(x));
    return r;
}

// ---------------- prep: zero counts/flags/alloc ----------------
__global__ void prep_zero(int* cntU, int* cntS, unsigned char* fu, unsigned char* fs, int* alloc2) {
    int i = blockIdx.x * blockDim.x + threadIdx.x;
    if (i < NUx) { cntU[i] = 0; fu[i] = 0; }
    if (i < NSx) { cntS[i] = 0; fs[i] = 0; }
    if (i < 2)   alloc2[i] = 0;
}

__global__ void flag_kernel(const int* __restrict__ mu, const int* __restrict__ ms,
                            unsigned char* __restrict__ fu, unsigned char* __restrict__ fs) {
    int m = blockIdx.x * blockDim.x + threadIdx.x;
    if (m >= NMx) return;
    fu[mu[m]] = 1;
    fs[ms[m]] = 1;
}

// ---------------- one-sided degree count ----------------
__global__ void count_one(const int* __restrict__ dst, int* __restrict__ cnt) {
    int e = blockIdx.x * blockDim.x + threadIdx.x;
    if (e >= NEx) return;
    atomicAdd(&cnt[dst[e]], 1);
}

// ---------------- CSR segment allocation (block scan + atomic bump) ----------------
__global__ void __launch_bounds__(256)
alloc_kernel(const int* __restrict__ cnt, int* __restrict__ off, int* __restrict__ cur,
             int N, int* __restrict__ alloc2, int cidx) {
    __shared__ int sc[256];
    __shared__ int base;
    int i = blockIdx.x * 256 + threadIdx.x;
    int v = (i < N) ? cnt[i] : 0;
    sc[threadIdx.x] = v;
    __syncthreads();
#pragma unroll
    for (int d = 1; d < 256; d <<= 1) {
        int t = (threadIdx.x >= d) ? sc[threadIdx.x - d] : 0;
        __syncthreads();
        sc[threadIdx.x] += t;
        __syncthreads();
    }
    if (threadIdx.x == 255) base = atomicAdd(&alloc2[cidx], sc[255]);
    __syncthreads();
    if (i < N) {
        int excl = sc[threadIdx.x] - v + base;
        off[i] = excl;
        cur[i] = excl;
    }
}

// ---------------- one-sided CSR fill ----------------
__global__ void fill_one(const int* __restrict__ src, const int* __restrict__ dst,
                         int* __restrict__ cur, int* __restrict__ csr) {
    int e = blockIdx.x * blockDim.x + threadIdx.x;
    if (e >= NEx) return;
    int d = dst[e];
    int p = atomicAdd(&cur[d], 1);
    csr[p] = src[e];
}

// ---------------- CSR gather ----------------
template<int LG, bool FLAG, bool XU>
__global__ void __launch_bounds__(256)
gather_rows(const float* __restrict__ feat, const int* __restrict__ csr,
            const int* __restrict__ off, const int* __restrict__ cnt,
            float* __restrict__ agg, int Nrows, const unsigned char* __restrict__ flag,
            const int* __restrict__ x1, const float* __restrict__ aemb,
            const float* __restrict__ gemb)
{
    constexpr int F4 = 1 << LG;
    long long g = (long long)blockIdx.x * blockDim.x + threadIdx.x;
    int r = (int)(g >> LG);
    if (r >= Nrows) return;
    if (FLAG && !flag[r]) return;
    const int c = threadIdx.x & (F4 - 1);
    const int o = off[r], n = cnt[r];

    auto ld = [&](int nb) -> float4 {
        if (XU) {
            if (c < 8)  return ((const float4*)aemb)[((const int2*)x1)[nb].x * 8 + c];
            if (c < 16) return ((const float4*)gemb)[((const int2*)x1)[nb].y * 8 + (c - 8)];
            return ((const float4*)feat)[(size_t)nb * 16 + (c - 16)];
        }
        return ((const float4*)feat)[(size_t)nb * F4 + c];
    };

    float4 acc = make_float4(0.f, 0.f, 0.f, 0.f);
    int i = 0;
    for (; i + 2 <= n; i += 2) {
        int nb0 = csr[o + i], nb1 = csr[o + i + 1];
        float4 a = ld(nb0);
        float4 b = ld(nb1);
        acc.x += a.x + b.x; acc.y += a.y + b.y;
        acc.z += a.z + b.z; acc.w += a.w + b.w;
    }
    if (i < n) {
        float4 a = ld(csr[o + i]);
        acc.x += a.x; acc.y += a.y; acc.z += a.z; acc.w += a.w;
    }
    ((float4*)agg)[(size_t)r * F4 + c] = acc;
}

// ---------------- build tf32 weight image in m16n8k8 B-fragment layout ----------------
__global__ void build_B_kernel(const float* __restrict__ Wl, const float* __restrict__ Wr,
                               int FA, int K, uint32_t* __restrict__ img) {
    int tid = blockIdx.x * blockDim.x + threadIdx.x;
    if (tid >= K * 128) return;
    int k = tid >> 7, n = tid & 127;
    float v = (k < FA) ? Wl[k * 128 + n] : Wr[(k - FA) * 128 + n];
    int ntile = n >> 3;
    int lane  = ((n & 7) << 2) | (k & 3);
    int reg   = (k >> 2) & 1;
    int kstep = k >> 3;
    img[((ntile * (K >> 3) + kstep) * 32 + lane) * 2 + reg] = f2tf32(v);
}

// ================= tf32 mma.sync GEMM core, 64-row M-tile, 2 CTAs/SM =========
// 8 warps: wm = wid&1 -> 32-row strip, wn = wid>>1 -> 32-col quarter.
template<int FA, int FB, bool DOT, bool GATHER, bool XUF>
__global__ void __launch_bounds__(256, 2)
gemm_mma(const float* __restrict__ agg, const int* __restrict__ cnt,
         const float* __restrict__ xr, const uint32_t* __restrict__ Bfrag,
         const float* __restrict__ bias, const float* __restrict__ lw,
         float* __restrict__ out, int Nrows, const int* __restrict__ mask,
         const int* __restrict__ x1, const float* __restrict__ aemb,
         const float* __restrict__ gemb)
{
    constexpr int K   = FA + FB;
    constexpr int KS  = K / 8;
    constexpr int LDA = K + 4;
    constexpr int J   = K / 16;   // float4s per staging thread (4 threads/row)

    extern __shared__ uint32_t sA[];   // [64][LDA] tf32 bits (+64 partials if DOT)
    float* part = (float*)(sA + 64 * LDA);
    const int tid  = threadIdx.x;
    const int wid  = tid >> 5;
    const int lane = tid & 31;
    const int tile0 = blockIdx.x * 64;

    // ---- stage A: 4 threads per row ----
    {
        const int row = tid >> 2;
        const int q   = tid & 3;
        int idx = tile0 + row; if (idx >= Nrows) idx = Nrows - 1;
        int grow = GATHER ? mask[idx] : idx;
        int c = cnt[grow];
        const float inv = 1.f / (float)(c > 1 ? c : 1);
        const float4* pa = (const float4*)(agg + (size_t)grow * FA);
        const float4* px = (const float4*)(xr  + (size_t)grow * FB);
        int ax = 0, gx = 0;
        if (XUF) { int2 xx = ((const int2*)x1)[grow]; ax = xx.x; gx = xx.y; }
#pragma unroll
        for (int j = 0; j < J; j++) {
            int k4 = q * J + j;
            int kf = k4 * 4;
            float4 v; float sc;
            if (kf < FA) { v = pa[k4]; sc = inv; }
            else if (XUF) {
                int cc = k4 - FA / 4;
                if (cc < 8)       v = ((const float4*)aemb)[ax * 8 + cc];
                else if (cc < 16) v = ((const float4*)gemb)[gx * 8 + (cc - 8)];
                else              v = ((const float4*)xr)[(size_t)grow * 16 + (cc - 16)];
                sc = 1.f;
            } else { v = px[k4 - FA / 4]; sc = 1.f; }
            uint4 t;
            t.x = f2tf32(v.x * sc); t.y = f2tf32(v.y * sc);
            t.z = f2tf32(v.z * sc); t.w = f2tf32(v.w * sc);
            *(uint4*)(sA + row * LDA + kf) = t;
        }
        if (DOT && tid < 64) part[tid] = 0.f;
    }
    __syncthreads();

    const int wm = wid & 1;
    const int wn = wid >> 1;
    const int lr = lane >> 2;
    const int lc = lane & 3;

    float acc[2][4][4];
#pragma unroll
    for (int t = 0; t < 2; t++)
#pragma unroll
        for (int nt = 0; nt < 4; nt++)
#pragma unroll
            for (int q = 0; q < 4; q++) acc[t][nt][q] = 0.f;

    const uint32_t* Ab = sA + (wm * 32 + lr) * LDA + lc;
    const uint2* Bp = (const uint2*)Bfrag + (size_t)(wn * 4) * KS * 32 + lane;

    uint2 bc[4], bn[4];
#pragma unroll
    for (int nt = 0; nt < 4; nt++) bc[nt] = Bp[nt * KS * 32];

#pragma unroll
    for (int ks = 0; ks < KS; ks++) {
        if (ks + 1 < KS) {
#pragma unroll
            for (int nt = 0; nt < 4; nt++) bn[nt] = Bp[nt * KS * 32 + (ks + 1) * 32];
        }
        uint32_t a[2][4];
#pragma unroll
        for (int t = 0; t < 2; t++) {
            const uint32_t* p = Ab + t * 16 * LDA + ks * 8;
            a[t][0] = p[0];
            a[t][1] = p[8 * LDA];
            a[t][2] = p[4];
            a[t][3] = p[8 * LDA + 4];
        }
#pragma unroll
        for (int t = 0; t < 2; t++)
#pragma unroll
            for (int nt = 0; nt < 4; nt++) {
                asm volatile(
                    "mma.sync.aligned.m16n8k8.row.col.f32.tf32.tf32.f32 "
                    "{%0,%1,%2,%3}, {%4,%5,%6,%7}, {%8,%9}, {%0,%1,%2,%3};"
                    : "+f"(acc[t][nt][0]), "+f"(acc[t][nt][1]),
                      "+f"(acc[t][nt][2]), "+f"(acc[t][nt][3])
                    : "r"(a[t][0]), "r"(a[t][1]), "r"(a[t][2]), "r"(a[t][3]),
                      "r"(bc[nt].x), "r"(bc[nt].y));
            }
#pragma unroll
        for (int nt = 0; nt < 4; nt++) bc[nt] = bn[nt];
    }

    if (!DOT) {
#pragma unroll
        for (int nt = 0; nt < 4; nt++) {
            const int col = wn * 32 + nt * 8 + lc * 2;
            const float2 bv = *(const float2*)(bias + col);
#pragma unroll
            for (int t = 0; t < 2; t++) {
                int r0 = tile0 + wm * 32 + t * 16 + lr;
                if (r0 < Nrows) {
                    float2 o;
                    o.x = fmaxf(acc[t][nt][0] + bv.x, 0.f);
                    o.y = fmaxf(acc[t][nt][1] + bv.y, 0.f);
                    *(float2*)(out + (size_t)r0 * 128 + col) = o;
                }
                int r1 = r0 + 8;
                if (r1 < Nrows) {
                    float2 o;
                    o.x = fmaxf(acc[t][nt][2] + bv.x, 0.f);
                    o.y = fmaxf(acc[t][nt][3] + bv.y, 0.f);
                    *(float2*)(out + (size_t)r1 * 128 + col) = o;
                }
            }
        }
    } else {
        float p[2][2] = {{0.f, 0.f}, {0.f, 0.f}};
#pragma unroll
        for (int nt = 0; nt < 4; nt++) {
            const int col = wn * 32 + nt * 8 + lc * 2;
            const float2 bv = *(const float2*)(bias + col);
            const float2 wv = *(const float2*)(lw + col);
#pragma unroll
            for (int t = 0; t < 2; t++) {
                p[t][0] += fmaxf(acc[t][nt][0] + bv.x, 0.f) * wv.x
                         + fmaxf(acc[t][nt][1] + bv.y, 0.f) * wv.y;
                p[t][1] += fmaxf(acc[t][nt][2] + bv.x, 0.f) * wv.x
                         + fmaxf(acc[t][nt][3] + bv.y, 0.f) * wv.y;
            }
        }
#pragma unroll
        for (int t = 0; t < 2; t++)
#pragma unroll
            for (int h = 0; h < 2; h++) {
                p[t][h] += __shfl_xor_sync(0xffffffffu, p[t][h], 1);
                p[t][h] += __shfl_xor_sync(0xffffffffu, p[t][h], 2);
            }
        if (lc == 0) {
#pragma unroll
            for (int t = 0; t < 2; t++) {
                atomicAdd(&part[wm * 32 + t * 16 + lr],     p[t][0]);
                atomicAdd(&part[wm * 32 + t * 16 + lr + 8], p[t][1]);
            }
        }
        __syncthreads();
        if (tid < 64) {
            int idx = tile0 + tid;
            if (idx < Nrows) out[idx] = part[tid];
        }
    }
}

// ---------------- head ----------------
__global__ void final_kernel(const int* __restrict__ ms,
                             const float* __restrict__ partU,
                             const float* __restrict__ dotS,
                             const float* __restrict__ lb,
                             float* __restrict__ out) {
    int m = blockIdx.x * blockDim.x + threadIdx.x;
    if (m >= NMx) return;
    float s = partU[m] + dotS[ms[m]] + lb[0];
    out[m] = 1.f / (1.f + expf(-s));
}

// ---------------- launcher ----------------
extern "C" void kernel_launch(void* const* d_in, const int* in_sizes, int n_in,
                              void* d_out, int out_size) {
    (void)in_sizes; (void)n_in; (void)out_size;
    const float* x_user_feat   = (const float*)d_in[0];
    const float* x_seller_feat = (const float*)d_in[1];
    const int*   x1            = (const int*)  d_in[2];
    const int*   src_user      = (const int*)  d_in[3];
    const int*   dst_seller    = (const int*)  d_in[4];
    const int*   src_seller    = (const int*)  d_in[5];
    const int*   dst_user      = (const int*)  d_in[6];
    const int*   mask_user     = (const int*)  d_in[7];
    const int*   mask_seller   = (const int*)  d_in[8];
    const float* age_emb       = (const float*)d_in[9];
    const float* gen_emb       = (const float*)d_in[10];
    const float* W1ul = (const float*)d_in[11];
    const float* W1ur = (const float*)d_in[12];
    const float* b1u  = (const float*)d_in[13];
    const float* W1sl = (const float*)d_in[14];
    const float* W1sr = (const float*)d_in[15];
    const float* b1s  = (const float*)d_in[16];
    const float* W2ul = (const float*)d_in[17];
    const float* W2ur = (const float*)d_in[18];
    const float* b2u  = (const float*)d_in[19];
    const float* W2sl = (const float*)d_in[20];
    const float* W2sr = (const float*)d_in[21];
    const float* b2s  = (const float*)d_in[22];
    const float* lin_w = (const float*)d_in[23];
    const float* lin_b = (const float*)d_in[24];
    float* out = (float*)d_out;

    float *aggU, *aggS, *aggU2, *aggS2, *u1, *s1, *partU, *dotS;
    int *cntU, *cntS, *offU, *offS, *curU, *curS, *csrU, *csrS, *alloc2;
    unsigned char *flagU, *flagS;
    uint32_t* Bimg;
    cudaGetSymbolAddress((void**)&aggU,  g_aggU);
    cudaGetSymbolAddress((void**)&aggS,  g_aggS);
    cudaGetSymbolAddress((void**)&aggU2, g_aggU2);
    cudaGetSymbolAddress((void**)&aggS2, g_aggS2);
    cudaGetSymbolAddress((void**)&u1,    g_u1);
    cudaGetSymbolAddress((void**)&s1,    g_s1);
    cudaGetSymbolAddress((void**)&partU, g_partU);
    cudaGetSymbolAddress((void**)&dotS,  g_dotS);
    cudaGetSymbolAddress((void**)&cntU,  g_cntU);
    cudaGetSymbolAddress((void**)&cntS,  g_cntS);
    cudaGetSymbolAddress((void**)&offU,  g_offU);
    cudaGetSymbolAddress((void**)&offS,  g_offS);
    cudaGetSymbolAddress((void**)&curU,  g_curU);
    cudaGetSymbolAddress((void**)&curS,  g_curS);
    cudaGetSymbolAddress((void**)&csrU,  g_csrU);
    cudaGetSymbolAddress((void**)&csrS,  g_csrS);
    cudaGetSymbolAddress((void**)&alloc2, g_alloc);
    cudaGetSymbolAddress((void**)&flagU, g_flagU);
    cudaGetSymbolAddress((void**)&flagS, g_flagS);
    cudaGetSymbolAddress((void**)&Bimg,  g_Bimg);

    const int SM192 = 64 * (192 + 4) * 4;          // 50176
    const int SM256 = 64 * (256 + 4) * 4 + 256;    // 66816
    cudaFuncSetAttribute((const void*)gemm_mma<64,128,false,false,true>,
                         cudaFuncAttributeMaxDynamicSharedMemorySize, SM192);
    cudaFuncSetAttribute((const void*)gemm_mma<128,64,false,false,false>,
                         cudaFuncAttributeMaxDynamicSharedMemorySize, SM192);
    cudaFuncSetAttribute((const void*)gemm_mma<128,128,true,true,false>,
                         cudaFuncAttributeMaxDynamicSharedMemorySize, SM256);
    cudaFuncSetAttribute((const void*)gemm_mma<128,128,true,false,false>,
                         cudaFuncAttributeMaxDynamicSharedMemorySize, SM256);

    static cudaStream_t s2 = nullptr;
    static cudaEvent_t evF, evPrep, evCSRS, evCSRU, evU1, evS1, evG2U;
    if (!s2) {
        cudaStreamCreateWithFlags(&s2, cudaStreamNonBlocking);
        cudaEventCreateWithFlags(&evF,    cudaEventDisableTiming);
        cudaEventCreateWithFlags(&evPrep, cudaEventDisableTiming);
        cudaEventCreateWithFlags(&evCSRS, cudaEventDisableTiming);
        cudaEventCreateWithFlags(&evCSRU, cudaEventDisableTiming);
        cudaEventCreateWithFlags(&evU1,   cudaEventDisableTiming);
        cudaEventCreateWithFlags(&evS1,   cudaEventDisableTiming);
        cudaEventCreateWithFlags(&evG2U,  cudaEventDisableTiming);
    }
    cudaStream_t s0 = 0;
    const int T = 256;

    // ---- fork ----
    cudaEventRecord(evF, s0);
    cudaStreamWaitEvent(s2, evF, 0);

    // ---- s0: shared prep (zeros, flags) ----
    prep_zero<<<(NUx + T - 1) / T, T, 0, s0>>>(cntU, cntS, flagU, flagS, alloc2);
    flag_kernel<<<(NMx + T - 1) / T, T, 0, s0>>>(mask_user, mask_seller, flagU, flagS);
    cudaEventRecord(evPrep, s0);

    // ---- s2: B images + seller-side CSR + seller L1 chain ----
    build_B_kernel<<<(192*128 + T - 1) / T, T, 0, s2>>>(W1sl, W1sr, 128, 192, Bimg + 1*32768);
    build_B_kernel<<<(256*128 + T - 1) / T, T, 0, s2>>>(W2ul, W2ur, 128, 256, Bimg + 2*32768);
    build_B_kernel<<<(256*128 + T - 1) / T, T, 0, s2>>>(W2sl, W2sr, 128, 256, Bimg + 3*32768);
    cudaStreamWaitEvent(s2, evPrep, 0);
    count_one<<<(NEx + T - 1) / T, T, 0, s2>>>(dst_seller, cntS);
    alloc_kernel<<<(NSx + 255) / 256, 256, 0, s2>>>(cntS, offS, curS, NSx, alloc2, 1);
    fill_one<<<(NEx + T - 1) / T, T, 0, s2>>>(src_user, dst_seller, curS, csrS);
    cudaEventRecord(evCSRS, s2);
    gather_rows<5,false,true><<<(NSx * 32 + T - 1) / T, T, 0, s2>>>(
        x_user_feat, csrS, offS, cntS, aggS, NSx, nullptr, x1, age_emb, gen_emb);
    gemm_mma<128,64,false,false,false><<<(NSx + 63) / 64, 256, SM192, s2>>>(
        aggS, cntS, x_seller_feat, Bimg + 1*32768, b1s, nullptr, s1, NSx, nullptr, nullptr, nullptr, nullptr);
    cudaEventRecord(evS1, s2);

    // ---- s0: user-side CSR + user L1 chain + L2 seller branch ----
    build_B_kernel<<<(192*128 + T - 1) / T, T, 0, s0>>>(W1ul, W1ur, 64, 192, Bimg + 0*32768);
    count_one<<<(NEx + T - 1) / T, T, 0, s0>>>(dst_user, cntU);
    alloc_kernel<<<(NUx + 255) / 256, 256, 0, s0>>>(cntU, offU, curU, NUx, alloc2, 0);
    fill_one<<<(NEx + T - 1) / T, T, 0, s0>>>(src_seller, dst_user, curU, csrU);
    cudaEventRecord(evCSRU, s0);
    gather_rows<4,false,false><<<(NUx * 16 + T - 1) / T, T, 0, s0>>>(
        x_seller_feat, csrU, offU, cntU, aggU, NUx, nullptr, nullptr, nullptr, nullptr);
    gemm_mma<64,128,false,false,true><<<(NUx + 63) / 64, 256, SM192, s0>>>(
        aggU, cntU, x_user_feat, Bimg + 0*32768, b1u, nullptr, u1, NUx, nullptr, x1, age_emb, gen_emb);
    cudaEventRecord(evU1, s0);
    cudaStreamWaitEvent(s0, evCSRS, 0);
    gather_rows<5,true,false><<<(NSx * 32 + T - 1) / T, T, 0, s0>>>(
        u1, csrS, offS, cntS, aggS2, NSx, flagS, nullptr, nullptr, nullptr);
    cudaStreamWaitEvent(s0, evS1, 0);
    gemm_mma<128,128,true,false,false><<<(NSx + 63) / 64, 256, SM256, s0>>>(
        aggS2, cntS, s1, Bimg + 3*32768, b2s, lin_w + 128, dotS, NSx, nullptr, nullptr, nullptr, nullptr);

    // ---- s2: L2 user branch (s1 local; csrU/flagU via events) ----
    cudaStreamWaitEvent(s2, evCSRU, 0);
    gather_rows<5,true,false><<<(NUx * 32 + T - 1) / T, T, 0, s2>>>(
        s1, csrU, offU, cntU, aggU2, NUx, flagU, nullptr, nullptr, nullptr);
    cudaStreamWaitEvent(s2, evU1, 0);
    gemm_mma<128,128,true,true,false><<<(NMx + 63) / 64, 256, SM256, s2>>>(
        aggU2, cntU, u1, Bimg + 2*32768, b2u, lin_w, partU, NMx, mask_user, nullptr, nullptr, nullptr);
    cudaEventRecord(evG2U, s2);

    // ---- join + head ----
    cudaStreamWaitEvent(s0, evG2U, 0);
    final_kernel<<<(NMx + T - 1) / T, T, 0, s0>>>(mask_seller, partU, dotS, lin_b, out);
}